// round 1
// baseline (speedup 1.0000x reference)
#include <cuda_runtime.h>

// ---------------- problem constants (fixed shapes for this problem) ----------------
#define B_    8
#define TTXT  40
#define SIMG  1024
#define NTOK  1064            // TTXT + SIMG
#define CDIM  768
#define H_    12
#define HD    64
#define K3    2304            // 3*CDIM
#define MROWS (B_*NTOK)       // 8512

// ---------------- scratch (static device globals; no runtime allocation) -----------
__device__ float g_q [B_*H_*NTOK*HD];   // [b][h][n][e]
__device__ float g_k [B_*H_*NTOK*HD];
__device__ float g_v [B_*H_*NTOK*HD];
__device__ float g_ao[MROWS*CDIM];      // attention output, [b*N + n][c]

// ====================================================================================
// Kernel 1: QKV GEMM.  qkv[m,d] = sum_c x[m,c]*qkv_w[d,c], scattered into g_q/g_k/g_v.
// Tiles: BM=64, BN=64, BK=16, 256 threads, 4x4 micro-tile per thread.
// ====================================================================================
__global__ __launch_bounds__(256) void qkv_kernel(const float* __restrict__ x,
                                                  const float* __restrict__ w)
{
    __shared__ float As[16][64];
    __shared__ float Ws[16][64];

    const int m0 = blockIdx.y * 64;
    const int n0 = blockIdx.x * 64;
    const int tid = threadIdx.x;
    const int tx = tid & 15;           // 0..15 -> 4 output cols
    const int ty = tid >> 4;           // 0..15 -> 4 output rows

    const int lm  = tid >> 2;          // 0..63 row within tile for loads
    const int lk4 = (tid & 3) * 4;     // 0,4,8,12 k offset

    const float* arow = x + (size_t)(m0 + lm) * CDIM + lk4;
    const float* wrow = w + (size_t)(n0 + lm) * CDIM + lk4;

    float acc[4][4] = {};

    for (int k0 = 0; k0 < CDIM; k0 += 16) {
        float4 av = *(const float4*)(arow + k0);
        float4 wv = *(const float4*)(wrow + k0);
        As[lk4+0][lm] = av.x;  As[lk4+1][lm] = av.y;
        As[lk4+2][lm] = av.z;  As[lk4+3][lm] = av.w;
        Ws[lk4+0][lm] = wv.x;  Ws[lk4+1][lm] = wv.y;
        Ws[lk4+2][lm] = wv.z;  Ws[lk4+3][lm] = wv.w;
        __syncthreads();
        #pragma unroll
        for (int k = 0; k < 16; k++) {
            float4 a = *(const float4*)&As[k][ty*4];
            float4 b = *(const float4*)&Ws[k][tx*4];
            acc[0][0] += a.x*b.x; acc[0][1] += a.x*b.y; acc[0][2] += a.x*b.z; acc[0][3] += a.x*b.w;
            acc[1][0] += a.y*b.x; acc[1][1] += a.y*b.y; acc[1][2] += a.y*b.z; acc[1][3] += a.y*b.w;
            acc[2][0] += a.z*b.x; acc[2][1] += a.z*b.y; acc[2][2] += a.z*b.z; acc[2][3] += a.z*b.w;
            acc[3][0] += a.w*b.x; acc[3][1] += a.w*b.y; acc[3][2] += a.w*b.z; acc[3][3] += a.w*b.w;
        }
        __syncthreads();
    }

    // scatter epilogue: d = s3*CDIM + h*HD + e ; dest layout [b][h][n][e]
    #pragma unroll
    for (int i = 0; i < 4; i++) {
        int m = m0 + ty*4 + i;
        int b = m / NTOK;
        int n = m - b * NTOK;
        #pragma unroll
        for (int j = 0; j < 4; j++) {
            int d   = n0 + tx*4 + j;
            int s3  = d / CDIM;
            int rem = d - s3 * CDIM;
            int h   = rem >> 6;
            int e   = rem & 63;
            float* dst = (s3 == 0) ? g_q : (s3 == 1) ? g_k : g_v;
            dst[((size_t)(b*H_ + h) * NTOK + n) * HD + e] = acc[i][j];
        }
    }
}

// ====================================================================================
// Kernel 2: text attention. One block per (b,h). q_mt/k_mt/v_mt = first TTXT tokens.
// ====================================================================================
__global__ __launch_bounds__(64) void text_attn_kernel()
{
    const int bh = blockIdx.x;
    const int b = bh / H_;
    const int h = bh - b * H_;

    __shared__ float Kt[TTXT][HD];
    __shared__ float Vt[TTXT][HD];

    const size_t base = (size_t)(b*H_ + h) * NTOK * HD;
    const float* kbase = g_k + base;
    const float* vbase = g_v + base;

    const int tid = threadIdx.x;
    for (int i = tid; i < TTXT*HD; i += 64) {
        Kt[i / HD][i % HD] = kbase[i];
        Vt[i / HD][i % HD] = vbase[i];
    }
    __syncthreads();

    if (tid < TTXT) {
        const float* qrow = g_q + base + (size_t)tid * HD;
        float qv[HD];
        #pragma unroll
        for (int e = 0; e < HD; e++) qv[e] = qrow[e];

        float sc[TTXT];
        float mx = -1e30f;
        #pragma unroll 4
        for (int s = 0; s < TTXT; s++) {
            float d = 0.f;
            #pragma unroll
            for (int e = 0; e < HD; e++) d += qv[e] * Kt[s][e];
            d *= 0.125f;           // 1/sqrt(64)
            sc[s] = d;
            mx = fmaxf(mx, d);
        }
        float sum = 0.f;
        #pragma unroll
        for (int s = 0; s < TTXT; s++) { sc[s] = __expf(sc[s] - mx); sum += sc[s]; }
        float inv = 1.f / sum;

        float* orow = g_ao + ((size_t)b * NTOK + tid) * CDIM + h * HD;
        #pragma unroll 4
        for (int e = 0; e < HD; e++) {
            float a = 0.f;
            #pragma unroll
            for (int s = 0; s < TTXT; s++) a += sc[s] * Vt[s][e];
            orow[e] = a * inv;
        }
    }
}

// ====================================================================================
// Kernel 3: image attention. Block = (b,h, 16 query rows). Full score strip in smem.
//   pass 1: scores[16][1088] = q_tile @ K^T * scale   (tiled over 17 key tiles of 64)
//   pass 2: warp-per-row softmax
//   pass 3: out = probs @ V (tiled over 17 value tiles)
// ====================================================================================
#define QT   16
#define KT   64
#define NKT  17               // ceil(1064/64)
#define SW   1088             // NKT*KT
#define KVP  68               // kv tile pitch (floats), 272B rows keep 16B alignment

#define IMG_SMEM ((QT*HD + QT*SW + KT*KVP) * 4)

__global__ __launch_bounds__(256) void img_attn_kernel()
{
    extern __shared__ float sm[];
    float* qs = sm;                    // [QT][HD]
    float* sc = sm + QT*HD;            // [QT][SW]
    float* kv = sc + QT*SW;            // [KT][KVP] (K transposed / V natural)

    const int bh = blockIdx.y;
    const int b = bh / H_;
    const int h = bh - b * H_;
    const int q0 = blockIdx.x * QT;    // image-row offset (0..1008)

    const int tid = threadIdx.x;
    const int tx = tid & 15;           // 4 output cols
    const int ty = tid >> 4;           // 1 output row (0..15)

    const size_t base = (size_t)(b*H_ + h) * NTOK * HD;
    const float* qbase = g_q + base + (size_t)(TTXT + q0) * HD;
    const float* kbase = g_k + base;
    const float* vbase = g_v + base;

    for (int i = tid; i < QT*HD; i += 256) qs[i] = qbase[i];

    // ---- pass 1: scores ----
    for (int t = 0; t < NKT; t++) {
        const int j0 = t * KT;
        __syncthreads();
        #pragma unroll
        for (int i = 0; i < 4; i++) {
            int lin = tid + i * 256;            // float4 units, 1024 total
            int j   = lin >> 4;
            int e4  = (lin & 15) * 4;
            int n   = j0 + j;
            float4 kk = (n < NTOK) ? *(const float4*)(kbase + (size_t)n*HD + e4)
                                   : make_float4(0.f,0.f,0.f,0.f);
            kv[(e4+0)*KVP + j] = kk.x;
            kv[(e4+1)*KVP + j] = kk.y;
            kv[(e4+2)*KVP + j] = kk.z;
            kv[(e4+3)*KVP + j] = kk.w;
        }
        __syncthreads();

        float a0=0.f, a1=0.f, a2=0.f, a3=0.f;
        #pragma unroll
        for (int e = 0; e < HD; e++) {
            float  qv = qs[ty*HD + e];
            float4 kk = *(const float4*)&kv[e*KVP + tx*4];
            a0 += qv*kk.x; a1 += qv*kk.y; a2 += qv*kk.z; a3 += qv*kk.w;
        }
        int nk = j0 + tx*4;
        float* srow = sc + ty*SW + nk;
        srow[0] = (nk+0 < NTOK) ? a0*0.125f : -1e30f;
        srow[1] = (nk+1 < NTOK) ? a1*0.125f : -1e30f;
        srow[2] = (nk+2 < NTOK) ? a2*0.125f : -1e30f;
        srow[3] = (nk+3 < NTOK) ? a3*0.125f : -1e30f;
    }
    __syncthreads();

    // ---- pass 2: softmax, warp per row (8 warps, 2 rows each) ----
    {
        const int wrp  = tid >> 5;
        const int lane = tid & 31;
        #pragma unroll
        for (int rr = 0; rr < 2; rr++) {
            float* row = sc + (wrp*2 + rr) * SW;
            float mx = -1e30f;
            for (int idx = lane; idx < SW; idx += 32) mx = fmaxf(mx, row[idx]);
            #pragma unroll
            for (int o = 16; o; o >>= 1) mx = fmaxf(mx, __shfl_xor_sync(0xffffffffu, mx, o));
            float s = 0.f;
            for (int idx = lane; idx < SW; idx += 32) {
                float p = __expf(row[idx] - mx);
                row[idx] = p;
                s += p;
            }
            #pragma unroll
            for (int o = 16; o; o >>= 1) s += __shfl_xor_sync(0xffffffffu, s, o);
            float inv = 1.f / s;
            for (int idx = lane; idx < SW; idx += 32) row[idx] *= inv;
        }
    }

    // ---- pass 3: PV ----
    float o0=0.f, o1=0.f, o2=0.f, o3=0.f;
    for (int t = 0; t < NKT; t++) {
        const int j0 = t * KT;
        __syncthreads();
        #pragma unroll
        for (int i = 0; i < 4; i++) {
            int lin = tid + i * 256;
            int s   = lin >> 4;
            int c4  = (lin & 15) * 4;
            int n   = j0 + s;
            float4 vv = (n < NTOK) ? *(const float4*)(vbase + (size_t)n*HD + c4)
                                   : make_float4(0.f,0.f,0.f,0.f);
            *(float4*)&kv[s*KVP + c4] = vv;
        }
        __syncthreads();
        #pragma unroll
        for (int s = 0; s < KT; s++) {
            float  p  = sc[ty*SW + j0 + s];
            float4 vv = *(const float4*)&kv[s*KVP + tx*4];
            o0 += p*vv.x; o1 += p*vv.y; o2 += p*vv.z; o3 += p*vv.w;
        }
    }

    float* dst = g_ao + ((size_t)b*NTOK + TTXT + q0 + ty) * CDIM + h*HD + tx*4;
    dst[0]=o0; dst[1]=o1; dst[2]=o2; dst[3]=o3;
}

// ====================================================================================
// Kernel 4: output projection. out[m,d] = sum_c ao[m,c]*proj_w[d,c] + proj_b[d]
// ====================================================================================
__global__ __launch_bounds__(256) void proj_kernel(const float* __restrict__ w,
                                                   const float* __restrict__ bias,
                                                   float* __restrict__ out)
{
    __shared__ float As[16][64];
    __shared__ float Ws[16][64];

    const int m0 = blockIdx.y * 64;
    const int n0 = blockIdx.x * 64;
    const int tid = threadIdx.x;
    const int tx = tid & 15;
    const int ty = tid >> 4;

    const int lm  = tid >> 2;
    const int lk4 = (tid & 3) * 4;

    const float* arow = g_ao + (size_t)(m0 + lm) * CDIM + lk4;
    const float* wrow = w    + (size_t)(n0 + lm) * CDIM + lk4;

    float acc[4][4] = {};

    for (int k0 = 0; k0 < CDIM; k0 += 16) {
        float4 av = *(const float4*)(arow + k0);
        float4 wv = *(const float4*)(wrow + k0);
        As[lk4+0][lm] = av.x;  As[lk4+1][lm] = av.y;
        As[lk4+2][lm] = av.z;  As[lk4+3][lm] = av.w;
        Ws[lk4+0][lm] = wv.x;  Ws[lk4+1][lm] = wv.y;
        Ws[lk4+2][lm] = wv.z;  Ws[lk4+3][lm] = wv.w;
        __syncthreads();
        #pragma unroll
        for (int k = 0; k < 16; k++) {
            float4 a = *(const float4*)&As[k][ty*4];
            float4 b = *(const float4*)&Ws[k][tx*4];
            acc[0][0] += a.x*b.x; acc[0][1] += a.x*b.y; acc[0][2] += a.x*b.z; acc[0][3] += a.x*b.w;
            acc[1][0] += a.y*b.x; acc[1][1] += a.y*b.y; acc[1][2] += a.y*b.z; acc[1][3] += a.y*b.w;
            acc[2][0] += a.z*b.x; acc[2][1] += a.z*b.y; acc[2][2] += a.z*b.z; acc[2][3] += a.z*b.w;
            acc[3][0] += a.w*b.x; acc[3][1] += a.w*b.y; acc[3][2] += a.w*b.z; acc[3][3] += a.w*b.w;
        }
        __syncthreads();
    }

    #pragma unroll
    for (int i = 0; i < 4; i++) {
        int m = m0 + ty*4 + i;
        #pragma unroll
        for (int j = 0; j < 4; j++) {
            int d = n0 + tx*4 + j;
            out[(size_t)m * CDIM + d] = acc[i][j] + bias[d];
        }
    }
}

// ====================================================================================
// launch
// ====================================================================================
extern "C" void kernel_launch(void* const* d_in, const int* in_sizes, int n_in,
                              void* d_out, int out_size)
{
    const float* x      = (const float*)d_in[0];
    const float* qkv_w  = (const float*)d_in[1];
    const float* proj_w = (const float*)d_in[2];
    const float* proj_b = (const float*)d_in[3];
    float* out = (float*)d_out;

    cudaFuncSetAttribute(img_attn_kernel,
                         cudaFuncAttributeMaxDynamicSharedMemorySize, IMG_SMEM);

    qkv_kernel   <<<dim3(K3/64,   MROWS/64), 256>>>(x, qkv_w);
    text_attn_kernel<<<B_*H_, 64>>>();
    img_attn_kernel <<<dim3(SIMG/QT, B_*H_), 256, IMG_SMEM>>>();
    proj_kernel  <<<dim3(CDIM/64, MROWS/64), 256>>>(proj_w, proj_b, out);
}

// round 5
// speedup vs baseline: 1.2340x; 1.2340x over previous
#include <cuda_runtime.h>
#include <cuda_bf16.h>
#include <cstdint>

// ---------------- problem constants ----------------
#define B_    8
#define TTXT  40
#define SIMG  1024
#define NTOK  1064
#define CDIM  768
#define H_    12
#define HD    64
#define MROWS (B_*NTOK)       // 8512
#define MPAD  8576            // 67*128
#define K3    (3*CDIM)        // 2304 : split-concatenated K
#define NQKV  (3*CDIM)        // 2304 : qkv output dim

// ---------------- device scratch (only referenced from device code!) ----------------
__device__ float g_q [B_*H_*NTOK*HD];
__device__ float g_k [B_*H_*NTOK*HD];
__device__ float g_v [B_*H_*NTOK*HD];

// split-concatenated bf16 operands: A-side = [hi | hi | lo], B-side = [hi | lo | hi]
__device__ __align__(16) __nv_bfloat16 gxc [MPAD*K3];
__device__ __align__(16) __nv_bfloat16 gw1c[NQKV*K3];
__device__ __align__(16) __nv_bfloat16 gw2c[CDIM*K3];
__device__ __align__(16) __nv_bfloat16 gaoc[MPAD*K3];

// ---------------- split/concat kernels (globals referenced in device code) ----------
__global__ __launch_bounds__(256) void split_x_kernel(const float* __restrict__ src)
{
    int i = blockIdx.x * 256 + threadIdx.x;
    if (i >= MPAD * CDIM) return;
    int row = i / CDIM, c = i - row * CDIM;
    float f = (row < MROWS) ? src[(size_t)row * CDIM + c] : 0.f;
    __nv_bfloat16 h = __float2bfloat16(f);
    __nv_bfloat16 l = __float2bfloat16(f - __bfloat162float(h));
    size_t base = (size_t)row * K3 + c;
    gxc[base]          = h;
    gxc[base + CDIM]   = h;
    gxc[base + 2*CDIM] = l;
}

__global__ __launch_bounds__(256) void split_w1_kernel(const float* __restrict__ src)
{
    int i = blockIdx.x * 256 + threadIdx.x;
    if (i >= NQKV * CDIM) return;
    int row = i / CDIM, c = i - row * CDIM;
    float f = src[(size_t)row * CDIM + c];
    __nv_bfloat16 h = __float2bfloat16(f);
    __nv_bfloat16 l = __float2bfloat16(f - __bfloat162float(h));
    size_t base = (size_t)row * K3 + c;
    gw1c[base]          = h;
    gw1c[base + CDIM]   = l;
    gw1c[base + 2*CDIM] = h;
}

__global__ __launch_bounds__(256) void split_w2_kernel(const float* __restrict__ src)
{
    int i = blockIdx.x * 256 + threadIdx.x;
    if (i >= CDIM * CDIM) return;
    int row = i / CDIM, c = i - row * CDIM;
    float f = src[(size_t)row * CDIM + c];
    __nv_bfloat16 h = __float2bfloat16(f);
    __nv_bfloat16 l = __float2bfloat16(f - __bfloat162float(h));
    size_t base = (size_t)row * K3 + c;
    gw2c[base]          = h;
    gw2c[base + CDIM]   = l;
    gw2c[base + 2*CDIM] = h;
}

// ---------------- warp mma ----------------
__device__ __forceinline__ void mma16816(float* d, const uint32_t* a, const uint32_t* b)
{
    asm volatile(
        "mma.sync.aligned.m16n8k16.row.col.f32.bf16.bf16.f32 "
        "{%0,%1,%2,%3}, {%4,%5,%6,%7}, {%8,%9}, {%0,%1,%2,%3};"
        : "+f"(d[0]), "+f"(d[1]), "+f"(d[2]), "+f"(d[3])
        : "r"(a[0]), "r"(a[1]), "r"(a[2]), "r"(a[3]), "r"(b[0]), "r"(b[1]));
}

// D[128,128] = A[rows@m0][K3] @ B[rows@n0][K3]^T, fp32 accum.
// 256 threads, warps 2(M)x4(N), warp tile 64x32 = 4x4 m16n8k16.
// Register-prefetch double-buffered smem, one __syncthreads per K tile.
__device__ __forceinline__ void gemm_main(const __nv_bfloat16* __restrict__ A,
                                          const __nv_bfloat16* __restrict__ B,
                                          int m0, int n0, float acc[4][4][4])
{
    __shared__ __align__(16) __nv_bfloat16 As[2][128][40];
    __shared__ __align__(16) __nv_bfloat16 Bs[2][128][40];

    const int tid  = threadIdx.x;
    const int lane = tid & 31, wid = tid >> 5;
    const int wm = (wid & 1) * 64;
    const int wn = (wid >> 1) * 32;
    const int g  = lane >> 2, tg = lane & 3;

    const int lr = tid >> 2;          // 0..63
    const int lk = (tid & 3) * 8;     // 0,8,16,24

    const __nv_bfloat16* Ap = A + (size_t)(m0 + lr) * K3 + lk;
    const __nv_bfloat16* Bp = B + (size_t)(n0 + lr) * K3 + lk;

    uint4 ra0, ra1, rb0, rb1;

    // prologue: tile 0 -> buf 0
    ra0 = *(const uint4*)(Ap);
    ra1 = *(const uint4*)(Ap + (size_t)64 * K3);
    rb0 = *(const uint4*)(Bp);
    rb1 = *(const uint4*)(Bp + (size_t)64 * K3);
    *(uint4*)&As[0][lr][lk]      = ra0;
    *(uint4*)&As[0][lr + 64][lk] = ra1;
    *(uint4*)&Bs[0][lr][lk]      = rb0;
    *(uint4*)&Bs[0][lr + 64][lk] = rb1;
    __syncthreads();

    const int NKI = K3 / 32;          // 72
    for (int t = 0; t < NKI; t++) {
        const int buf = t & 1;
        if (t + 1 < NKI) {
            const size_t o = (size_t)(t + 1) * 32;
            ra0 = *(const uint4*)(Ap + o);
            ra1 = *(const uint4*)(Ap + o + (size_t)64 * K3);
            rb0 = *(const uint4*)(Bp + o);
            rb1 = *(const uint4*)(Bp + o + (size_t)64 * K3);
        }
        #pragma unroll
        for (int ks = 0; ks < 2; ks++) {
            const int kb = ks * 16 + tg * 2;
            uint32_t af[4][4], bfr[4][2];
            #pragma unroll
            for (int mt = 0; mt < 4; mt++) {
                const int r = wm + mt * 16 + g;
                af[mt][0] = *(const uint32_t*)&As[buf][r][kb];
                af[mt][1] = *(const uint32_t*)&As[buf][r + 8][kb];
                af[mt][2] = *(const uint32_t*)&As[buf][r][kb + 8];
                af[mt][3] = *(const uint32_t*)&As[buf][r + 8][kb + 8];
            }
            #pragma unroll
            for (int nt = 0; nt < 4; nt++) {
                const int n = wn + nt * 8 + g;
                bfr[nt][0] = *(const uint32_t*)&Bs[buf][n][kb];
                bfr[nt][1] = *(const uint32_t*)&Bs[buf][n][kb + 8];
            }
            #pragma unroll
            for (int mt = 0; mt < 4; mt++)
                #pragma unroll
                for (int nt = 0; nt < 4; nt++)
                    mma16816(acc[mt][nt], af[mt], bfr[nt]);
        }
        if (t + 1 < NKI) {
            const int nb = buf ^ 1;
            *(uint4*)&As[nb][lr][lk]      = ra0;
            *(uint4*)&As[nb][lr + 64][lk] = ra1;
            *(uint4*)&Bs[nb][lr][lk]      = rb0;
            *(uint4*)&Bs[nb][lr + 64][lk] = rb1;
        }
        __syncthreads();
    }
}

// ---------------- QKV GEMM kernel: fused scatter epilogue ----------------
__global__ __launch_bounds__(256) void qkv_gemm_kernel()
{
    const int n0 = blockIdx.x * 128;   // over 2304
    const int m0 = blockIdx.y * 128;   // over MPAD

    float acc[4][4][4] = {};
    gemm_main(gxc, gw1c, m0, n0, acc);

    const int lane = threadIdx.x & 31, wid = threadIdx.x >> 5;
    const int wm = (wid & 1) * 64, wn = (wid >> 1) * 32;
    const int g = lane >> 2, tg = lane & 3;

    const int s3    = n0 / CDIM;       // 128-wide tile never straddles q/k/v
    const int nrem0 = n0 - s3 * CDIM;
    float* dstm = (s3 == 0) ? g_q : (s3 == 1) ? g_k : g_v;

    #pragma unroll
    for (int mt = 0; mt < 4; mt++) {
        #pragma unroll
        for (int nt = 0; nt < 4; nt++) {
            const int col = nrem0 + wn + nt * 8 + tg * 2;
            const int h = col >> 6, e = col & 63;   // even col: pair stays in one head
            #pragma unroll
            for (int rr = 0; rr < 2; rr++) {
                const int m = m0 + wm + mt * 16 + g + rr * 8;
                if (m >= MROWS) continue;
                const int b = m / NTOK;
                const int n = m - b * NTOK;
                float* dst = dstm + ((size_t)(b * H_ + h) * NTOK + n) * HD + e;
                dst[0] = acc[mt][nt][rr * 2 + 0];
                dst[1] = acc[mt][nt][rr * 2 + 1];
            }
        }
    }
}

// ---------------- proj GEMM kernel ----------------
__global__ __launch_bounds__(256) void proj_gemm_kernel(const float* __restrict__ bias,
                                                        float* __restrict__ out)
{
    const int n0 = blockIdx.x * 128;   // over 768
    const int m0 = blockIdx.y * 128;

    float acc[4][4][4] = {};
    gemm_main(gaoc, gw2c, m0, n0, acc);

    const int lane = threadIdx.x & 31, wid = threadIdx.x >> 5;
    const int wm = (wid & 1) * 64, wn = (wid >> 1) * 32;
    const int g = lane >> 2, tg = lane & 3;

    #pragma unroll
    for (int mt = 0; mt < 4; mt++) {
        #pragma unroll
        for (int nt = 0; nt < 4; nt++) {
            const int d = n0 + wn + nt * 8 + tg * 2;
            const float b0 = bias[d], b1 = bias[d + 1];
            #pragma unroll
            for (int rr = 0; rr < 2; rr++) {
                const int m = m0 + wm + mt * 16 + g + rr * 8;
                if (m >= MROWS) continue;
                out[(size_t)m * CDIM + d]     = acc[mt][nt][rr * 2 + 0] + b0;
                out[(size_t)m * CDIM + d + 1] = acc[mt][nt][rr * 2 + 1] + b1;
            }
        }
    }
}

// ---------------- attention output split-store (A-side layout: hi|hi|lo) ----------
__device__ __forceinline__ void store_split3(int row, int c, float v)
{
    __nv_bfloat16 h = __float2bfloat16(v);
    __nv_bfloat16 l = __float2bfloat16(v - __bfloat162float(h));
    size_t base = (size_t)row * K3 + c;
    gaoc[base]          = h;
    gaoc[base + CDIM]   = h;
    gaoc[base + 2*CDIM] = l;
}

// ---------------- text attention ----------------
__global__ __launch_bounds__(64) void text_attn_kernel()
{
    const int bh = blockIdx.x;
    const int b = bh / H_;
    const int h = bh - b * H_;

    __shared__ float Kt[TTXT][HD];
    __shared__ float Vt[TTXT][HD];

    const size_t base = (size_t)(b*H_ + h) * NTOK * HD;
    const float* kbase = g_k + base;
    const float* vbase = g_v + base;

    const int tid = threadIdx.x;
    for (int i = tid; i < TTXT*HD; i += 64) {
        Kt[i / HD][i % HD] = kbase[i];
        Vt[i / HD][i % HD] = vbase[i];
    }
    __syncthreads();

    if (tid < TTXT) {
        const float* qrow = g_q + base + (size_t)tid * HD;
        float qv[HD];
        #pragma unroll
        for (int e = 0; e < HD; e++) qv[e] = qrow[e];

        float sc[TTXT];
        float mx = -1e30f;
        #pragma unroll 4
        for (int s = 0; s < TTXT; s++) {
            float d = 0.f;
            #pragma unroll
            for (int e = 0; e < HD; e++) d += qv[e] * Kt[s][e];
            d *= 0.125f;
            sc[s] = d;
            mx = fmaxf(mx, d);
        }
        float sum = 0.f;
        #pragma unroll
        for (int s = 0; s < TTXT; s++) { sc[s] = __expf(sc[s] - mx); sum += sc[s]; }
        float inv = 1.f / sum;

        const int row = b * NTOK + tid;
        #pragma unroll 4
        for (int e = 0; e < HD; e++) {
            float a = 0.f;
            #pragma unroll
            for (int s = 0; s < TTXT; s++) a += sc[s] * Vt[s][e];
            store_split3(row, h * HD + e, a * inv);
        }
    }
}

// ---------------- image attention ----------------
#define QT   16
#define KT   64
#define NKT  17
#define SW   1088
#define KVP  68
#define IMG_SMEM ((QT*HD + QT*SW + KT*KVP) * 4)

__global__ __launch_bounds__(256) void img_attn_kernel()
{
    extern __shared__ float smf[];
    float* qs = smf;
    float* sc = smf + QT*HD;
    float* kv = sc + QT*SW;

    const int bh = blockIdx.y;
    const int b = bh / H_;
    const int h = bh - b * H_;
    const int q0 = blockIdx.x * QT;

    const int tid = threadIdx.x;
    const int tx = tid & 15;
    const int ty = tid >> 4;

    const size_t base = (size_t)(b*H_ + h) * NTOK * HD;
    const float* qbase = g_q + base + (size_t)(TTXT + q0) * HD;
    const float* kbase = g_k + base;
    const float* vbase = g_v + base;

    for (int i = tid; i < QT*HD; i += 256) qs[i] = qbase[i];

    for (int t = 0; t < NKT; t++) {
        const int j0 = t * KT;
        __syncthreads();
        #pragma unroll
        for (int i = 0; i < 4; i++) {
            int lin = tid + i * 256;
            int j   = lin >> 4;
            int e4  = (lin & 15) * 4;
            int n   = j0 + j;
            float4 kk = (n < NTOK) ? *(const float4*)(kbase + (size_t)n*HD + e4)
                                   : make_float4(0.f,0.f,0.f,0.f);
            kv[(e4+0)*KVP + j] = kk.x;
            kv[(e4+1)*KVP + j] = kk.y;
            kv[(e4+2)*KVP + j] = kk.z;
            kv[(e4+3)*KVP + j] = kk.w;
        }
        __syncthreads();

        float a0=0.f, a1=0.f, a2=0.f, a3=0.f;
        #pragma unroll
        for (int e = 0; e < HD; e++) {
            float  qv = qs[ty*HD + e];
            float4 kk = *(const float4*)&kv[e*KVP + tx*4];
            a0 += qv*kk.x; a1 += qv*kk.y; a2 += qv*kk.z; a3 += qv*kk.w;
        }
        int nk = j0 + tx*4;
        float* srow = sc + ty*SW + nk;
        srow[0] = (nk+0 < NTOK) ? a0*0.125f : -1e30f;
        srow[1] = (nk+1 < NTOK) ? a1*0.125f : -1e30f;
        srow[2] = (nk+2 < NTOK) ? a2*0.125f : -1e30f;
        srow[3] = (nk+3 < NTOK) ? a3*0.125f : -1e30f;
    }
    __syncthreads();

    {
        const int wrp  = tid >> 5;
        const int lane = tid & 31;
        #pragma unroll
        for (int rr = 0; rr < 2; rr++) {
            float* row = sc + (wrp*2 + rr) * SW;
            float mx = -1e30f;
            for (int idx = lane; idx < SW; idx += 32) mx = fmaxf(mx, row[idx]);
            #pragma unroll
            for (int o = 16; o; o >>= 1) mx = fmaxf(mx, __shfl_xor_sync(0xffffffffu, mx, o));
            float s = 0.f;
            for (int idx = lane; idx < SW; idx += 32) {
                float p = __expf(row[idx] - mx);
                row[idx] = p;
                s += p;
            }
            #pragma unroll
            for (int o = 16; o; o >>= 1) s += __shfl_xor_sync(0xffffffffu, s, o);
            float inv = 1.f / s;
            for (int idx = lane; idx < SW; idx += 32) row[idx] *= inv;
        }
    }

    float o0=0.f, o1=0.f, o2=0.f, o3=0.f;
    for (int t = 0; t < NKT; t++) {
        const int j0 = t * KT;
        __syncthreads();
        #pragma unroll
        for (int i = 0; i < 4; i++) {
            int lin = tid + i * 256;
            int s   = lin >> 4;
            int c4  = (lin & 15) * 4;
            int n   = j0 + s;
            float4 vv = (n < NTOK) ? *(const float4*)(vbase + (size_t)n*HD + c4)
                                   : make_float4(0.f,0.f,0.f,0.f);
            *(float4*)&kv[s*KVP + c4] = vv;
        }
        __syncthreads();
        #pragma unroll
        for (int s = 0; s < KT; s++) {
            float  p  = sc[ty*SW + j0 + s];
            float4 vv = *(const float4*)&kv[s*KVP + tx*4];
            o0 += p*vv.x; o1 += p*vv.y; o2 += p*vv.z; o3 += p*vv.w;
        }
    }

    const int row = b*NTOK + TTXT + q0 + ty;
    const int c   = h*HD + tx*4;
    store_split3(row, c+0, o0);
    store_split3(row, c+1, o1);
    store_split3(row, c+2, o2);
    store_split3(row, c+3, o3);
}

// ---------------- launch ----------------
extern "C" void kernel_launch(void* const* d_in, const int* in_sizes, int n_in,
                              void* d_out, int out_size)
{
    const float* x      = (const float*)d_in[0];
    const float* qkv_w  = (const float*)d_in[1];
    const float* proj_w = (const float*)d_in[2];
    const float* proj_b = (const float*)d_in[3];
    float* out = (float*)d_out;

    cudaFuncSetAttribute(img_attn_kernel, cudaFuncAttributeMaxDynamicSharedMemorySize, IMG_SMEM);

    split_x_kernel <<<(MPAD*CDIM + 255)/256, 256>>>(x);
    split_w1_kernel<<<(NQKV*CDIM + 255)/256, 256>>>(qkv_w);
    split_w2_kernel<<<(CDIM*CDIM + 255)/256, 256>>>(proj_w);

    qkv_gemm_kernel<<<dim3(NQKV/128, MPAD/128), 256>>>();

    text_attn_kernel<<<B_*H_, 64>>>();
    img_attn_kernel <<<dim3(SIMG/QT, B_*H_), 256, IMG_SMEM>>>();

    proj_gemm_kernel<<<dim3(CDIM/128, MPAD/128), 256>>>(proj_b, out);
}

// round 6
// speedup vs baseline: 3.2324x; 2.6195x over previous
#include <cuda_runtime.h>
#include <cuda_bf16.h>
#include <cstdint>

// ---------------- problem constants ----------------
#define B_    8
#define TTXT  40
#define SIMG  1024
#define NTOK  1064
#define CDIM  768
#define H_    12
#define HD    64
#define MROWS (B_*NTOK)       // 8512
#define MPAD  8576            // 67*128
#define K3    (3*CDIM)        // 2304 : split-concatenated K
#define NQKV  (3*CDIM)        // 2304

// ---------------- device scratch (referenced ONLY from device code) ----------------
// fp32 q/k/v kept only for text tokens (n < TTXT), but sized simply.
__device__ float g_q [B_*H_*NTOK*HD];
__device__ float g_k [B_*H_*NTOK*HD];
__device__ float g_v [B_*H_*NTOK*HD];

// GEMM operands, split-concatenated along K (A-side hi|hi|lo, B-side hi|lo|hi)
__device__ __align__(16) __nv_bfloat16 gxc [MPAD*K3];
__device__ __align__(16) __nv_bfloat16 gw1c[NQKV*K3];
__device__ __align__(16) __nv_bfloat16 gw2c[CDIM*K3];
__device__ __align__(16) __nv_bfloat16 gaoc[MPAD*K3];

// attention operands
__device__ __align__(16) __nv_bfloat16 g_qc [B_*H_*NTOK*192];  // [bh][n][hi|hi|lo]
__device__ __align__(16) __nv_bfloat16 g_kc [B_*H_*NTOK*192];  // [bh][n][hi|lo|hi]
__device__ __align__(16) __nv_bfloat16 g_vht[B_*H_*HD*NTOK];   // V^T hi: [bh][e][n]
__device__ __align__(16) __nv_bfloat16 g_vlt[B_*H_*HD*NTOK];   // V^T lo

// ---------------- split/concat kernels ----------------
__global__ __launch_bounds__(256) void split_x_kernel(const float* __restrict__ src)
{
    int i = blockIdx.x * 256 + threadIdx.x;
    if (i >= MPAD * CDIM) return;
    int row = i / CDIM, c = i - row * CDIM;
    float f = (row < MROWS) ? src[(size_t)row * CDIM + c] : 0.f;
    __nv_bfloat16 h = __float2bfloat16(f);
    __nv_bfloat16 l = __float2bfloat16(f - __bfloat162float(h));
    size_t base = (size_t)row * K3 + c;
    gxc[base]          = h;
    gxc[base + CDIM]   = h;
    gxc[base + 2*CDIM] = l;
}

__global__ __launch_bounds__(256) void split_w1_kernel(const float* __restrict__ src)
{
    int i = blockIdx.x * 256 + threadIdx.x;
    if (i >= NQKV * CDIM) return;
    int row = i / CDIM, c = i - row * CDIM;
    float f = src[(size_t)row * CDIM + c];
    __nv_bfloat16 h = __float2bfloat16(f);
    __nv_bfloat16 l = __float2bfloat16(f - __bfloat162float(h));
    size_t base = (size_t)row * K3 + c;
    gw1c[base]          = h;
    gw1c[base + CDIM]   = l;
    gw1c[base + 2*CDIM] = h;
}

__global__ __launch_bounds__(256) void split_w2_kernel(const float* __restrict__ src)
{
    int i = blockIdx.x * 256 + threadIdx.x;
    if (i >= CDIM * CDIM) return;
    int row = i / CDIM, c = i - row * CDIM;
    float f = src[(size_t)row * CDIM + c];
    __nv_bfloat16 h = __float2bfloat16(f);
    __nv_bfloat16 l = __float2bfloat16(f - __bfloat162float(h));
    size_t base = (size_t)row * K3 + c;
    gw2c[base]          = h;
    gw2c[base + CDIM]   = l;
    gw2c[base + 2*CDIM] = h;
}

// ---------------- warp mma ----------------
__device__ __forceinline__ void mma16816(float* d, const uint32_t* a, const uint32_t* b)
{
    asm volatile(
        "mma.sync.aligned.m16n8k16.row.col.f32.bf16.bf16.f32 "
        "{%0,%1,%2,%3}, {%4,%5,%6,%7}, {%8,%9}, {%0,%1,%2,%3};"
        : "+f"(d[0]), "+f"(d[1]), "+f"(d[2]), "+f"(d[3])
        : "r"(a[0]), "r"(a[1]), "r"(a[2]), "r"(a[3]), "r"(b[0]), "r"(b[1]));
}

// D[128,128] = A[rows@m0][K3] @ B[rows@n0][K3]^T, fp32 accum. (validated round 5)
__device__ __forceinline__ void gemm_main(const __nv_bfloat16* __restrict__ A,
                                          const __nv_bfloat16* __restrict__ B,
                                          int m0, int n0, float acc[4][4][4])
{
    __shared__ __align__(16) __nv_bfloat16 As[2][128][40];
    __shared__ __align__(16) __nv_bfloat16 Bs[2][128][40];

    const int tid  = threadIdx.x;
    const int lane = tid & 31, wid = tid >> 5;
    const int wm = (wid & 1) * 64;
    const int wn = (wid >> 1) * 32;
    const int g  = lane >> 2, tg = lane & 3;

    const int lr = tid >> 2;
    const int lk = (tid & 3) * 8;

    const __nv_bfloat16* Ap = A + (size_t)(m0 + lr) * K3 + lk;
    const __nv_bfloat16* Bp = B + (size_t)(n0 + lr) * K3 + lk;

    uint4 ra0, ra1, rb0, rb1;

    ra0 = *(const uint4*)(Ap);
    ra1 = *(const uint4*)(Ap + (size_t)64 * K3);
    rb0 = *(const uint4*)(Bp);
    rb1 = *(const uint4*)(Bp + (size_t)64 * K3);
    *(uint4*)&As[0][lr][lk]      = ra0;
    *(uint4*)&As[0][lr + 64][lk] = ra1;
    *(uint4*)&Bs[0][lr][lk]      = rb0;
    *(uint4*)&Bs[0][lr + 64][lk] = rb1;
    __syncthreads();

    const int NKI = K3 / 32;
    for (int t = 0; t < NKI; t++) {
        const int buf = t & 1;
        if (t + 1 < NKI) {
            const size_t o = (size_t)(t + 1) * 32;
            ra0 = *(const uint4*)(Ap + o);
            ra1 = *(const uint4*)(Ap + o + (size_t)64 * K3);
            rb0 = *(const uint4*)(Bp + o);
            rb1 = *(const uint4*)(Bp + o + (size_t)64 * K3);
        }
        #pragma unroll
        for (int ks = 0; ks < 2; ks++) {
            const int kb = ks * 16 + tg * 2;
            uint32_t af[4][4], bfr[4][2];
            #pragma unroll
            for (int mt = 0; mt < 4; mt++) {
                const int r = wm + mt * 16 + g;
                af[mt][0] = *(const uint32_t*)&As[buf][r][kb];
                af[mt][1] = *(const uint32_t*)&As[buf][r + 8][kb];
                af[mt][2] = *(const uint32_t*)&As[buf][r][kb + 8];
                af[mt][3] = *(const uint32_t*)&As[buf][r + 8][kb + 8];
            }
            #pragma unroll
            for (int nt = 0; nt < 4; nt++) {
                const int n = wn + nt * 8 + g;
                bfr[nt][0] = *(const uint32_t*)&Bs[buf][n][kb];
                bfr[nt][1] = *(const uint32_t*)&Bs[buf][n][kb + 8];
            }
            #pragma unroll
            for (int mt = 0; mt < 4; mt++)
                #pragma unroll
                for (int nt = 0; nt < 4; nt++)
                    mma16816(acc[mt][nt], af[mt], bfr[nt]);
        }
        if (t + 1 < NKI) {
            const int nb = buf ^ 1;
            *(uint4*)&As[nb][lr][lk]      = ra0;
            *(uint4*)&As[nb][lr + 64][lk] = ra1;
            *(uint4*)&Bs[nb][lr][lk]      = rb0;
            *(uint4*)&Bs[nb][lr + 64][lk] = rb1;
        }
        __syncthreads();
    }
}

// ---------------- QKV GEMM: epilogue writes attention-ready layouts ----------------
__global__ __launch_bounds__(256) void qkv_gemm_kernel()
{
    const int n0 = blockIdx.x * 128;
    const int m0 = blockIdx.y * 128;

    float acc[4][4][4] = {};
    gemm_main(gxc, gw1c, m0, n0, acc);

    const int lane = threadIdx.x & 31, wid = threadIdx.x >> 5;
    const int wm = (wid & 1) * 64, wn = (wid >> 1) * 32;
    const int g = lane >> 2, tg = lane & 3;

    const int s3    = n0 / CDIM;
    const int nrem0 = n0 - s3 * CDIM;

    #pragma unroll
    for (int mt = 0; mt < 4; mt++) {
        #pragma unroll
        for (int nt = 0; nt < 4; nt++) {
            const int col = nrem0 + wn + nt * 8 + tg * 2;
            const int hh = col >> 6, e = col & 63;
            #pragma unroll
            for (int rr = 0; rr < 2; rr++) {
                const int mm = m0 + wm + mt * 16 + g + rr * 8;
                if (mm >= MROWS) continue;
                const int b = mm / NTOK;
                const int n = mm - b * NTOK;
                const size_t idx = (size_t)(b * H_ + hh) * NTOK + n;
                const float v0 = acc[mt][nt][rr * 2 + 0];
                const float v1 = acc[mt][nt][rr * 2 + 1];
                const __nv_bfloat16 h0 = __float2bfloat16(v0);
                const __nv_bfloat16 h1 = __float2bfloat16(v1);
                const __nv_bfloat16 l0 = __float2bfloat16(v0 - __bfloat162float(h0));
                const __nv_bfloat16 l1 = __float2bfloat16(v1 - __bfloat162float(h1));
                if (s3 == 0) {
                    __nv_bfloat16* qd = g_qc + idx * 192 + e;
                    qd[0]   = h0; qd[1]   = h1;
                    qd[64]  = h0; qd[65]  = h1;
                    qd[128] = l0; qd[129] = l1;
                    if (n < TTXT) { g_q[idx*HD + e] = v0; g_q[idx*HD + e + 1] = v1; }
                } else if (s3 == 1) {
                    __nv_bfloat16* kd = g_kc + idx * 192 + e;
                    kd[0]   = h0; kd[1]   = h1;
                    kd[64]  = l0; kd[65]  = l1;
                    kd[128] = h0; kd[129] = h1;
                    if (n < TTXT) { g_k[idx*HD + e] = v0; g_k[idx*HD + e + 1] = v1; }
                } else {
                    const size_t vi = ((size_t)(b * H_ + hh) * HD + e) * NTOK + n;
                    g_vht[vi]        = h0;
                    g_vht[vi + NTOK] = h1;
                    g_vlt[vi]        = l0;
                    g_vlt[vi + NTOK] = l1;
                    if (n < TTXT) { g_v[idx*HD + e] = v0; g_v[idx*HD + e + 1] = v1; }
                }
            }
        }
    }
}

// ---------------- proj GEMM kernel ----------------
__global__ __launch_bounds__(256) void proj_gemm_kernel(const float* __restrict__ bias,
                                                        float* __restrict__ out)
{
    const int n0 = blockIdx.x * 128;
    const int m0 = blockIdx.y * 128;

    float acc[4][4][4] = {};
    gemm_main(gaoc, gw2c, m0, n0, acc);

    const int lane = threadIdx.x & 31, wid = threadIdx.x >> 5;
    const int wm = (wid & 1) * 64, wn = (wid >> 1) * 32;
    const int g = lane >> 2, tg = lane & 3;

    #pragma unroll
    for (int mt = 0; mt < 4; mt++) {
        #pragma unroll
        for (int nt = 0; nt < 4; nt++) {
            const int d = n0 + wn + nt * 8 + tg * 2;
            const float b0 = bias[d], b1 = bias[d + 1];
            #pragma unroll
            for (int rr = 0; rr < 2; rr++) {
                const int m = m0 + wm + mt * 16 + g + rr * 8;
                if (m >= MROWS) continue;
                out[(size_t)m * CDIM + d]     = acc[mt][nt][rr * 2 + 0] + b0;
                out[(size_t)m * CDIM + d + 1] = acc[mt][nt][rr * 2 + 1] + b1;
            }
        }
    }
}

// ---------------- gaoc split-store (A-side hi|hi|lo) ----------------
__device__ __forceinline__ void store_split3(int row, int c, float v)
{
    __nv_bfloat16 h = __float2bfloat16(v);
    __nv_bfloat16 l = __float2bfloat16(v - __bfloat162float(h));
    size_t base = (size_t)row * K3 + c;
    gaoc[base]          = h;
    gaoc[base + CDIM]   = h;
    gaoc[base + 2*CDIM] = l;
}

// ---------------- text attention (fp32, tiny) ----------------
__global__ __launch_bounds__(64) void text_attn_kernel()
{
    const int bh = blockIdx.x;
    const int b = bh / H_;
    const int h = bh - b * H_;

    __shared__ float Kt[TTXT][HD];
    __shared__ float Vt[TTXT][HD];

    const size_t base = (size_t)(b*H_ + h) * NTOK * HD;
    const float* kbase = g_k + base;
    const float* vbase = g_v + base;

    const int tid = threadIdx.x;
    for (int i = tid; i < TTXT*HD; i += 64) {
        Kt[i / HD][i % HD] = kbase[i];
        Vt[i / HD][i % HD] = vbase[i];
    }
    __syncthreads();

    if (tid < TTXT) {
        const float* qrow = g_q + base + (size_t)tid * HD;
        float qv[HD];
        #pragma unroll
        for (int e = 0; e < HD; e++) qv[e] = qrow[e];

        float sc[TTXT];
        float mx = -1e30f;
        #pragma unroll 4
        for (int s = 0; s < TTXT; s++) {
            float d = 0.f;
            #pragma unroll
            for (int e = 0; e < HD; e++) d += qv[e] * Kt[s][e];
            d *= 0.125f;
            sc[s] = d;
            mx = fmaxf(mx, d);
        }
        float sum = 0.f;
        #pragma unroll
        for (int s = 0; s < TTXT; s++) { sc[s] = __expf(sc[s] - mx); sum += sc[s]; }
        float inv = 1.f / sum;

        const int row = b * NTOK + tid;
        #pragma unroll 4
        for (int e = 0; e < HD; e++) {
            float a = 0.f;
            #pragma unroll
            for (int s = 0; s < TTXT; s++) a += sc[s] * Vt[s][e];
            store_split3(row, h * HD + e, a * inv);
        }
    }
}

// ---------------- image attention: mma flash kernel ----------------
// block = 64 image queries of one (b,h); 4 warps x 16 rows; 17 key tiles of 64.
#define QPITCH 200
#define VPITCH 72
#define OFF_K  25600
#define OFF_VH 51200
#define OFF_VL 60416
#define IMG_SMEM2 69632

__device__ __forceinline__ void pack_hilo(float x, float y, uint32_t& hi, uint32_t& lo)
{
    __nv_bfloat162 h = __floats2bfloat162_rn(x, y);
    float hx = __bfloat162float(h.x), hy = __bfloat162float(h.y);
    __nv_bfloat162 l = __floats2bfloat162_rn(x - hx, y - hy);
    hi = *(uint32_t*)&h;
    lo = *(uint32_t*)&l;
}

__global__ __launch_bounds__(128) void img_attn_mma_kernel()
{
    extern __shared__ char smx[];
    __nv_bfloat16* Qs = (__nv_bfloat16*)(smx);            // [64][200]
    __nv_bfloat16* Ks = (__nv_bfloat16*)(smx + OFF_K);    // [64][200]
    __nv_bfloat16* Vh = (__nv_bfloat16*)(smx + OFF_VH);   // [64][72]  (V^T hi)
    __nv_bfloat16* Vl = (__nv_bfloat16*)(smx + OFF_VL);   // [64][72]  (V^T lo)

    const int bh = blockIdx.y;
    const int q0 = blockIdx.x * 64;       // image-query offset
    const int tid = threadIdx.x;
    const int lane = tid & 31, wid = tid >> 5;
    const int g = lane >> 2, tg = lane & 3;
    const int wrow = wid * 16;

    // load Q tile (64 rows x 192)
    {
        const __nv_bfloat16* qsrc = g_qc + ((size_t)bh * NTOK + TTXT + q0) * 192;
        for (int u = tid; u < 64 * 24; u += 128) {
            int r = u / 24, o = (u % 24) * 8;
            *(uint4*)&Qs[r * QPITCH + o] = *(const uint4*)(qsrc + (size_t)r * 192 + o);
        }
    }

    float m0v = -1e30f, m1v = -1e30f, l0s = 0.f, l1s = 0.f;
    float O[8][4];
    #pragma unroll
    for (int nt = 0; nt < 8; nt++)
        #pragma unroll
        for (int j = 0; j < 4; j++) O[nt][j] = 0.f;

    const __nv_bfloat16* kcb = g_kc + (size_t)bh * NTOK * 192;
    const __nv_bfloat16* vhb = g_vht + (size_t)bh * HD * NTOK;
    const __nv_bfloat16* vlb = g_vlt + (size_t)bh * HD * NTOK;

    for (int t = 0; t < 17; t++) {
        const int j0 = t * 64;
        __syncthreads();   // previous tile fully consumed (also orders Q load)

        // K tile: 64 keys x 192
        for (int u = tid; u < 64 * 24; u += 128) {
            int r = u / 24, o = (u % 24) * 8;
            uint4 val = make_uint4(0u, 0u, 0u, 0u);
            if (j0 + r < NTOK)
                val = *(const uint4*)(kcb + (size_t)(j0 + r) * 192 + o);
            *(uint4*)&Ks[r * QPITCH + o] = val;
        }
        // V^T tiles: 64 dims x 64 keys (rows already transposed in gmem)
        for (int u = tid; u < 64 * 8; u += 128) {
            int e = u >> 3, o = (u & 7) * 8;
            uint4 vhv = make_uint4(0u, 0u, 0u, 0u);
            uint4 vlv = make_uint4(0u, 0u, 0u, 0u);
            if (j0 + o + 7 < NTOK) {       // NTOK - j0 is a multiple of 8 within the valid range
                vhv = *(const uint4*)(vhb + (size_t)e * NTOK + j0 + o);
                vlv = *(const uint4*)(vlb + (size_t)e * NTOK + j0 + o);
            }
            *(uint4*)&Vh[e * VPITCH + o] = vhv;
            *(uint4*)&Vl[e * VPITCH + o] = vlv;
        }
        __syncthreads();

        // ---- scores: S[16 x 64] per warp via 12 k-steps (192 split) ----
        float S[8][4];
        #pragma unroll
        for (int nt = 0; nt < 8; nt++)
            #pragma unroll
            for (int j = 0; j < 4; j++) S[nt][j] = 0.f;

        #pragma unroll
        for (int ks = 0; ks < 12; ks++) {
            const int kb = ks * 16 + tg * 2;
            uint32_t a[4];
            a[0] = *(const uint32_t*)&Qs[(wrow + g)     * QPITCH + kb];
            a[1] = *(const uint32_t*)&Qs[(wrow + g + 8) * QPITCH + kb];
            a[2] = *(const uint32_t*)&Qs[(wrow + g)     * QPITCH + kb + 8];
            a[3] = *(const uint32_t*)&Qs[(wrow + g + 8) * QPITCH + kb + 8];
            #pragma unroll
            for (int nt = 0; nt < 8; nt++) {
                uint32_t bb[2];
                bb[0] = *(const uint32_t*)&Ks[(nt * 8 + g) * QPITCH + kb];
                bb[1] = *(const uint32_t*)&Ks[(nt * 8 + g) * QPITCH + kb + 8];
                mma16816(S[nt], a, bb);
            }
        }

        // scale + mask invalid keys
        #pragma unroll
        for (int nt = 0; nt < 8; nt++) {
            const int key = j0 + nt * 8 + tg * 2;
            const bool v0 = key < NTOK, v1 = key + 1 < NTOK;
            S[nt][0] = v0 ? S[nt][0] * 0.125f : -1e30f;
            S[nt][1] = v1 ? S[nt][1] * 0.125f : -1e30f;
            S[nt][2] = v0 ? S[nt][2] * 0.125f : -1e30f;
            S[nt][3] = v1 ? S[nt][3] * 0.125f : -1e30f;
        }

        // online softmax
        float t0 = -1e30f, t1 = -1e30f;
        #pragma unroll
        for (int nt = 0; nt < 8; nt++) {
            t0 = fmaxf(t0, fmaxf(S[nt][0], S[nt][1]));
            t1 = fmaxf(t1, fmaxf(S[nt][2], S[nt][3]));
        }
        t0 = fmaxf(t0, __shfl_xor_sync(0xffffffffu, t0, 1));
        t0 = fmaxf(t0, __shfl_xor_sync(0xffffffffu, t0, 2));
        t1 = fmaxf(t1, __shfl_xor_sync(0xffffffffu, t1, 1));
        t1 = fmaxf(t1, __shfl_xor_sync(0xffffffffu, t1, 2));

        const float mn0 = fmaxf(m0v, t0), mn1 = fmaxf(m1v, t1);
        const float al0 = __expf(m0v - mn0), al1 = __expf(m1v - mn1);
        m0v = mn0; m1v = mn1;

        float rs0 = 0.f, rs1 = 0.f;
        #pragma unroll
        for (int nt = 0; nt < 8; nt++) {
            S[nt][0] = __expf(S[nt][0] - mn0);
            S[nt][1] = __expf(S[nt][1] - mn0);
            S[nt][2] = __expf(S[nt][2] - mn1);
            S[nt][3] = __expf(S[nt][3] - mn1);
            rs0 += S[nt][0] + S[nt][1];
            rs1 += S[nt][2] + S[nt][3];
        }
        rs0 += __shfl_xor_sync(0xffffffffu, rs0, 1);
        rs0 += __shfl_xor_sync(0xffffffffu, rs0, 2);
        rs1 += __shfl_xor_sync(0xffffffffu, rs1, 1);
        rs1 += __shfl_xor_sync(0xffffffffu, rs1, 2);
        l0s = l0s * al0 + rs0;
        l1s = l1s * al1 + rs1;

        #pragma unroll
        for (int nt = 0; nt < 8; nt++) {
            O[nt][0] *= al0; O[nt][1] *= al0;
            O[nt][2] *= al1; O[nt][3] *= al1;
        }

        // pack P into A-fragments (hi + lo)
        uint32_t ph[4][4], pl[4][4];
        #pragma unroll
        for (int ks = 0; ks < 4; ks++) {
            pack_hilo(S[2*ks][0],   S[2*ks][1],   ph[ks][0], pl[ks][0]);
            pack_hilo(S[2*ks][2],   S[2*ks][3],   ph[ks][1], pl[ks][1]);
            pack_hilo(S[2*ks+1][0], S[2*ks+1][1], ph[ks][2], pl[ks][2]);
            pack_hilo(S[2*ks+1][2], S[2*ks+1][3], ph[ks][3], pl[ks][3]);
        }

        // ---- PV: O[16 x 64] += P @ V  (3-term split) ----
        #pragma unroll
        for (int ks = 0; ks < 4; ks++) {
            const int kb = ks * 16 + tg * 2;
            #pragma unroll
            for (int nt = 0; nt < 8; nt++) {
                uint32_t bh2[2], bl2[2];
                bh2[0] = *(const uint32_t*)&Vh[(nt * 8 + g) * VPITCH + kb];
                bh2[1] = *(const uint32_t*)&Vh[(nt * 8 + g) * VPITCH + kb + 8];
                bl2[0] = *(const uint32_t*)&Vl[(nt * 8 + g) * VPITCH + kb];
                bl2[1] = *(const uint32_t*)&Vl[(nt * 8 + g) * VPITCH + kb + 8];
                mma16816(O[nt], ph[ks], bh2);
                mma16816(O[nt], ph[ks], bl2);
                mma16816(O[nt], pl[ks], bh2);
            }
        }
    }

    // epilogue
    const float inv0 = 1.f / l0s, inv1 = 1.f / l1s;
    const int b = bh / H_, h = bh - b * H_;
    const int row0 = b * NTOK + TTXT + q0 + wrow + g;
    const int row1 = row0 + 8;
    #pragma unroll
    for (int nt = 0; nt < 8; nt++) {
        const int c = h * HD + nt * 8 + tg * 2;
        store_split3(row0, c,     O[nt][0] * inv0);
        store_split3(row0, c + 1, O[nt][1] * inv0);
        store_split3(row1, c,     O[nt][2] * inv1);
        store_split3(row1, c + 1, O[nt][3] * inv1);
    }
}

// ---------------- launch ----------------
extern "C" void kernel_launch(void* const* d_in, const int* in_sizes, int n_in,
                              void* d_out, int out_size)
{
    const float* x      = (const float*)d_in[0];
    const float* qkv_w  = (const float*)d_in[1];
    const float* proj_w = (const float*)d_in[2];
    const float* proj_b = (const float*)d_in[3];
    float* out = (float*)d_out;

    cudaFuncSetAttribute(img_attn_mma_kernel,
                         cudaFuncAttributeMaxDynamicSharedMemorySize, IMG_SMEM2);

    split_x_kernel <<<(MPAD*CDIM + 255)/256, 256>>>(x);
    split_w1_kernel<<<(NQKV*CDIM + 255)/256, 256>>>(qkv_w);
    split_w2_kernel<<<(CDIM*CDIM + 255)/256, 256>>>(proj_w);

    qkv_gemm_kernel<<<dim3(NQKV/128, MPAD/128), 256>>>();

    text_attn_kernel<<<B_*H_, 64>>>();
    img_attn_mma_kernel<<<dim3(SIMG/64, B_*H_), 128, IMG_SMEM2>>>();

    proj_gemm_kernel<<<dim3(CDIM/128, MPAD/128), 256>>>(proj_b, out);
}

// round 7
// speedup vs baseline: 3.4562x; 1.0692x over previous
#include <cuda_runtime.h>
#include <cuda_bf16.h>
#include <cstdint>

// ---------------- problem constants ----------------
#define B_    8
#define TTXT  40
#define SIMG  1024
#define NTOK  1064
#define CDIM  768
#define H_    12
#define HD    64
#define MROWS (B_*NTOK)       // 8512
#define MPAD  8576            // 67*128
#define K3    (3*CDIM)        // 2304
#define NQKV  (3*CDIM)        // 2304

// ---------------- device scratch (referenced ONLY from device code) ----------------
__device__ float g_q [B_*H_*NTOK*HD];
__device__ float g_k [B_*H_*NTOK*HD];
__device__ float g_v [B_*H_*NTOK*HD];

__device__ __align__(16) __nv_bfloat16 gxc [MPAD*K3];
__device__ __align__(16) __nv_bfloat16 gw1c[NQKV*K3];
__device__ __align__(16) __nv_bfloat16 gw2c[CDIM*K3];
__device__ __align__(16) __nv_bfloat16 gaoc[MPAD*K3];

__device__ __align__(16) __nv_bfloat16 g_qc [B_*H_*NTOK*192];  // [bh][n][hi|hi|lo]
__device__ __align__(16) __nv_bfloat16 g_kc [B_*H_*NTOK*192];  // [bh][n][hi|lo|hi]
__device__ __align__(16) __nv_bfloat16 g_vht[B_*H_*HD*NTOK];   // V^T hi: [bh][e][n]
__device__ __align__(16) __nv_bfloat16 g_vlt[B_*H_*HD*NTOK];   // V^T lo

// ---------------- split/concat kernels ----------------
__global__ __launch_bounds__(256) void split_x_kernel(const float* __restrict__ src)
{
    int i = blockIdx.x * 256 + threadIdx.x;
    if (i >= MPAD * CDIM) return;
    int row = i / CDIM, c = i - row * CDIM;
    float f = (row < MROWS) ? src[(size_t)row * CDIM + c] : 0.f;
    __nv_bfloat16 h = __float2bfloat16(f);
    __nv_bfloat16 l = __float2bfloat16(f - __bfloat162float(h));
    size_t base = (size_t)row * K3 + c;
    gxc[base]          = h;
    gxc[base + CDIM]   = h;
    gxc[base + 2*CDIM] = l;
}

__global__ __launch_bounds__(256) void split_w1_kernel(const float* __restrict__ src)
{
    int i = blockIdx.x * 256 + threadIdx.x;
    if (i >= NQKV * CDIM) return;
    int row = i / CDIM, c = i - row * CDIM;
    float f = src[(size_t)row * CDIM + c];
    __nv_bfloat16 h = __float2bfloat16(f);
    __nv_bfloat16 l = __float2bfloat16(f - __bfloat162float(h));
    size_t base = (size_t)row * K3 + c;
    gw1c[base]          = h;
    gw1c[base + CDIM]   = l;
    gw1c[base + 2*CDIM] = h;
}

__global__ __launch_bounds__(256) void split_w2_kernel(const float* __restrict__ src)
{
    int i = blockIdx.x * 256 + threadIdx.x;
    if (i >= CDIM * CDIM) return;
    int row = i / CDIM, c = i - row * CDIM;
    float f = src[(size_t)row * CDIM + c];
    __nv_bfloat16 h = __float2bfloat16(f);
    __nv_bfloat16 l = __float2bfloat16(f - __bfloat162float(h));
    size_t base = (size_t)row * K3 + c;
    gw2c[base]          = h;
    gw2c[base + CDIM]   = l;
    gw2c[base + 2*CDIM] = h;
}

// ---------------- warp mma ----------------
__device__ __forceinline__ void mma16816(float* d, const uint32_t* a, const uint32_t* b)
{
    asm volatile(
        "mma.sync.aligned.m16n8k16.row.col.f32.bf16.bf16.f32 "
        "{%0,%1,%2,%3}, {%4,%5,%6,%7}, {%8,%9}, {%0,%1,%2,%3};"
        : "+f"(d[0]), "+f"(d[1]), "+f"(d[2]), "+f"(d[3])
        : "r"(a[0]), "r"(a[1]), "r"(a[2]), "r"(a[3]), "r"(b[0]), "r"(b[1]));
}

// D[128,128] = A[rows@m0][K3] @ B[rows@n0][K3]^T, fp32 accum.
// 128 threads, 4 warps 2x2, warp tile 64x64 (mt4 x nt8).
__device__ __forceinline__ void gemm_main(const __nv_bfloat16* __restrict__ A,
                                          const __nv_bfloat16* __restrict__ B,
                                          int m0, int n0, float acc[4][8][4])
{
    __shared__ __align__(16) __nv_bfloat16 As[2][128][40];
    __shared__ __align__(16) __nv_bfloat16 Bs[2][128][40];

    const int tid  = threadIdx.x;
    const int lane = tid & 31, wid = tid >> 5;
    const int wm = (wid & 1) * 64;
    const int wn = (wid >> 1) * 64;
    const int g  = lane >> 2, tg = lane & 3;

    const int lr = tid >> 2;          // 0..31
    const int lk = (tid & 3) * 8;     // 0,8,16,24

    const __nv_bfloat16* Ap = A + (size_t)(m0 + lr) * K3 + lk;
    const __nv_bfloat16* Bp = B + (size_t)(n0 + lr) * K3 + lk;

    uint4 ra[4], rb[4];

    // prologue: tile 0 -> buf 0
    #pragma unroll
    for (int i = 0; i < 4; i++) {
        ra[i] = *(const uint4*)(Ap + (size_t)(32*i) * K3);
        rb[i] = *(const uint4*)(Bp + (size_t)(32*i) * K3);
    }
    #pragma unroll
    for (int i = 0; i < 4; i++) {
        *(uint4*)&As[0][lr + 32*i][lk] = ra[i];
        *(uint4*)&Bs[0][lr + 32*i][lk] = rb[i];
    }
    __syncthreads();

    const int NKI = K3 / 32;          // 72
    for (int t = 0; t < NKI; t++) {
        const int buf = t & 1;
        if (t + 1 < NKI) {
            const size_t o = (size_t)(t + 1) * 32;
            #pragma unroll
            for (int i = 0; i < 4; i++) {
                ra[i] = *(const uint4*)(Ap + o + (size_t)(32*i) * K3);
                rb[i] = *(const uint4*)(Bp + o + (size_t)(32*i) * K3);
            }
        }
        #pragma unroll
        for (int ks = 0; ks < 2; ks++) {
            const int kb = ks * 16 + tg * 2;
            uint32_t af[4][4], bfr[8][2];
            #pragma unroll
            for (int mt = 0; mt < 4; mt++) {
                const int r = wm + mt * 16 + g;
                af[mt][0] = *(const uint32_t*)&As[buf][r][kb];
                af[mt][1] = *(const uint32_t*)&As[buf][r + 8][kb];
                af[mt][2] = *(const uint32_t*)&As[buf][r][kb + 8];
                af[mt][3] = *(const uint32_t*)&As[buf][r + 8][kb + 8];
            }
            #pragma unroll
            for (int nt = 0; nt < 8; nt++) {
                const int n = wn + nt * 8 + g;
                bfr[nt][0] = *(const uint32_t*)&Bs[buf][n][kb];
                bfr[nt][1] = *(const uint32_t*)&Bs[buf][n][kb + 8];
            }
            #pragma unroll
            for (int mt = 0; mt < 4; mt++)
                #pragma unroll
                for (int nt = 0; nt < 8; nt++)
                    mma16816(acc[mt][nt], af[mt], bfr[nt]);
        }
        if (t + 1 < NKI) {
            const int nb = buf ^ 1;
            #pragma unroll
            for (int i = 0; i < 4; i++) {
                *(uint4*)&As[nb][lr + 32*i][lk] = ra[i];
                *(uint4*)&Bs[nb][lr + 32*i][lk] = rb[i];
            }
        }
        __syncthreads();
    }
}

// ---------------- QKV GEMM: epilogue writes attention-ready layouts ----------------
__global__ __launch_bounds__(128) void qkv_gemm_kernel()
{
    const int n0 = blockIdx.x * 128;
    const int m0 = blockIdx.y * 128;

    float acc[4][8][4] = {};
    gemm_main(gxc, gw1c, m0, n0, acc);

    const int lane = threadIdx.x & 31, wid = threadIdx.x >> 5;
    const int wm = (wid & 1) * 64, wn = (wid >> 1) * 64;
    const int g = lane >> 2, tg = lane & 3;

    const int s3    = n0 / CDIM;
    const int nrem0 = n0 - s3 * CDIM;

    #pragma unroll
    for (int mt = 0; mt < 4; mt++) {
        #pragma unroll
        for (int nt = 0; nt < 8; nt++) {
            const int col = nrem0 + wn + nt * 8 + tg * 2;
            const int hh = col >> 6, e = col & 63;
            #pragma unroll
            for (int rr = 0; rr < 2; rr++) {
                const int mm = m0 + wm + mt * 16 + g + rr * 8;
                if (mm >= MROWS) continue;
                const int b = mm / NTOK;
                const int n = mm - b * NTOK;
                const size_t idx = (size_t)(b * H_ + hh) * NTOK + n;
                const float v0 = acc[mt][nt][rr * 2 + 0];
                const float v1 = acc[mt][nt][rr * 2 + 1];
                const __nv_bfloat16 h0 = __float2bfloat16(v0);
                const __nv_bfloat16 h1 = __float2bfloat16(v1);
                const __nv_bfloat16 l0 = __float2bfloat16(v0 - __bfloat162float(h0));
                const __nv_bfloat16 l1 = __float2bfloat16(v1 - __bfloat162float(h1));
                if (s3 == 0) {
                    __nv_bfloat16* qd = g_qc + idx * 192 + e;
                    qd[0]   = h0; qd[1]   = h1;
                    qd[64]  = h0; qd[65]  = h1;
                    qd[128] = l0; qd[129] = l1;
                    if (n < TTXT) { g_q[idx*HD + e] = v0; g_q[idx*HD + e + 1] = v1; }
                } else if (s3 == 1) {
                    __nv_bfloat16* kd = g_kc + idx * 192 + e;
                    kd[0]   = h0; kd[1]   = h1;
                    kd[64]  = l0; kd[65]  = l1;
                    kd[128] = h0; kd[129] = h1;
                    if (n < TTXT) { g_k[idx*HD + e] = v0; g_k[idx*HD + e + 1] = v1; }
                } else {
                    const size_t vi = ((size_t)(b * H_ + hh) * HD + e) * NTOK + n;
                    g_vht[vi]        = h0;
                    g_vht[vi + NTOK] = h1;
                    g_vlt[vi]        = l0;
                    g_vlt[vi + NTOK] = l1;
                    if (n < TTXT) { g_v[idx*HD + e] = v0; g_v[idx*HD + e + 1] = v1; }
                }
            }
        }
    }
}

// ---------------- proj GEMM kernel ----------------
__global__ __launch_bounds__(128) void proj_gemm_kernel(const float* __restrict__ bias,
                                                        float* __restrict__ out)
{
    const int n0 = blockIdx.x * 128;
    const int m0 = blockIdx.y * 128;

    float acc[4][8][4] = {};
    gemm_main(gaoc, gw2c, m0, n0, acc);

    const int lane = threadIdx.x & 31, wid = threadIdx.x >> 5;
    const int wm = (wid & 1) * 64, wn = (wid >> 1) * 64;
    const int g = lane >> 2, tg = lane & 3;

    #pragma unroll
    for (int mt = 0; mt < 4; mt++) {
        #pragma unroll
        for (int nt = 0; nt < 8; nt++) {
            const int d = n0 + wn + nt * 8 + tg * 2;
            const float b0 = bias[d], b1 = bias[d + 1];
            #pragma unroll
            for (int rr = 0; rr < 2; rr++) {
                const int m = m0 + wm + mt * 16 + g + rr * 8;
                if (m >= MROWS) continue;
                out[(size_t)m * CDIM + d]     = acc[mt][nt][rr * 2 + 0] + b0;
                out[(size_t)m * CDIM + d + 1] = acc[mt][nt][rr * 2 + 1] + b1;
            }
        }
    }
}

// ---------------- gaoc split-store (A-side hi|hi|lo) ----------------
__device__ __forceinline__ void store_split3(int row, int c, float v)
{
    __nv_bfloat16 h = __float2bfloat16(v);
    __nv_bfloat16 l = __float2bfloat16(v - __bfloat162float(h));
    size_t base = (size_t)row * K3 + c;
    gaoc[base]          = h;
    gaoc[base + CDIM]   = h;
    gaoc[base + 2*CDIM] = l;
}

// ---------------- text attention (fp32, tiny) ----------------
__global__ __launch_bounds__(64) void text_attn_kernel()
{
    const int bh = blockIdx.x;
    const int b = bh / H_;
    const int h = bh - b * H_;

    __shared__ float Kt[TTXT][HD];
    __shared__ float Vt[TTXT][HD];

    const size_t base = (size_t)(b*H_ + h) * NTOK * HD;
    const float* kbase = g_k + base;
    const float* vbase = g_v + base;

    const int tid = threadIdx.x;
    for (int i = tid; i < TTXT*HD; i += 64) {
        Kt[i / HD][i % HD] = kbase[i];
        Vt[i / HD][i % HD] = vbase[i];
    }
    __syncthreads();

    if (tid < TTXT) {
        const float* qrow = g_q + base + (size_t)tid * HD;
        float qv[HD];
        #pragma unroll
        for (int e = 0; e < HD; e++) qv[e] = qrow[e];

        float sc[TTXT];
        float mx = -1e30f;
        #pragma unroll 4
        for (int s = 0; s < TTXT; s++) {
            float d = 0.f;
            #pragma unroll
            for (int e = 0; e < HD; e++) d += qv[e] * Kt[s][e];
            d *= 0.125f;
            sc[s] = d;
            mx = fmaxf(mx, d);
        }
        float sum = 0.f;
        #pragma unroll
        for (int s = 0; s < TTXT; s++) { sc[s] = __expf(sc[s] - mx); sum += sc[s]; }
        float inv = 1.f / sum;

        const int row = b * NTOK + tid;
        #pragma unroll 4
        for (int e = 0; e < HD; e++) {
            float a = 0.f;
            #pragma unroll
            for (int s = 0; s < TTXT; s++) a += sc[s] * Vt[s][e];
            store_split3(row, h * HD + e, a * inv);
        }
    }
}

// ---------------- image attention: mma flash kernel (128-query blocks) ----------------
#define QPITCH 200
#define VPITCH 72
#define OFF_K  51200
#define OFF_VH 76800
#define OFF_VL 86016
#define IMG_SMEM2 95232

__device__ __forceinline__ void pack_hilo(float x, float y, uint32_t& hi, uint32_t& lo)
{
    __nv_bfloat162 h = __floats2bfloat162_rn(x, y);
    float hx = __bfloat162float(h.x), hy = __bfloat162float(h.y);
    __nv_bfloat162 l = __floats2bfloat162_rn(x - hx, y - hy);
    hi = *(uint32_t*)&h;
    lo = *(uint32_t*)&l;
}

__global__ __launch_bounds__(128) void img_attn_mma_kernel()
{
    extern __shared__ char smx[];
    __nv_bfloat16* Qs = (__nv_bfloat16*)(smx);            // [128][200]
    __nv_bfloat16* Ks = (__nv_bfloat16*)(smx + OFF_K);    // [64][200]
    __nv_bfloat16* Vh = (__nv_bfloat16*)(smx + OFF_VH);   // [64][72]
    __nv_bfloat16* Vl = (__nv_bfloat16*)(smx + OFF_VL);   // [64][72]

    const int bh = blockIdx.y;
    const int q0 = blockIdx.x * 128;      // image-query offset
    const int tid = threadIdx.x;
    const int lane = tid & 31, wid = tid >> 5;
    const int g = lane >> 2, tg = lane & 3;
    const int wrow = wid * 32;            // 32 query rows per warp (mt=2)

    // load Q tile (128 rows x 192)
    {
        const __nv_bfloat16* qsrc = g_qc + ((size_t)bh * NTOK + TTXT + q0) * 192;
        for (int u = tid; u < 128 * 24; u += 128) {
            int r = u / 24, o = (u % 24) * 8;
            *(uint4*)&Qs[r * QPITCH + o] = *(const uint4*)(qsrc + (size_t)r * 192 + o);
        }
    }

    float mrow[2][2], lrow[2][2];
    #pragma unroll
    for (int mt = 0; mt < 2; mt++) { mrow[mt][0] = mrow[mt][1] = -1e30f; lrow[mt][0] = lrow[mt][1] = 0.f; }

    float O[2][8][4];
    #pragma unroll
    for (int mt = 0; mt < 2; mt++)
        #pragma unroll
        for (int nt = 0; nt < 8; nt++)
            #pragma unroll
            for (int j = 0; j < 4; j++) O[mt][nt][j] = 0.f;

    const __nv_bfloat16* kcb = g_kc + (size_t)bh * NTOK * 192;
    const __nv_bfloat16* vhb = g_vht + (size_t)bh * HD * NTOK;
    const __nv_bfloat16* vlb = g_vlt + (size_t)bh * HD * NTOK;

    for (int t = 0; t < 17; t++) {
        const int j0 = t * 64;
        __syncthreads();

        // K tile: 64 keys x 192
        for (int u = tid; u < 64 * 24; u += 128) {
            int r = u / 24, o = (u % 24) * 8;
            uint4 val = make_uint4(0u, 0u, 0u, 0u);
            if (j0 + r < NTOK)
                val = *(const uint4*)(kcb + (size_t)(j0 + r) * 192 + o);
            *(uint4*)&Ks[r * QPITCH + o] = val;
        }
        // V^T tiles: 64 dims x 64 keys
        for (int u = tid; u < 64 * 8; u += 128) {
            int e = u >> 3, o = (u & 7) * 8;
            uint4 vhv = make_uint4(0u, 0u, 0u, 0u);
            uint4 vlv = make_uint4(0u, 0u, 0u, 0u);
            if (j0 + o + 7 < NTOK) {
                vhv = *(const uint4*)(vhb + (size_t)e * NTOK + j0 + o);
                vlv = *(const uint4*)(vlb + (size_t)e * NTOK + j0 + o);
            }
            *(uint4*)&Vh[e * VPITCH + o] = vhv;
            *(uint4*)&Vl[e * VPITCH + o] = vlv;
        }
        __syncthreads();

        // ---- scores: S[2][8][4] = 32 rows x 64 keys per warp ----
        float S[2][8][4];
        #pragma unroll
        for (int mt = 0; mt < 2; mt++)
            #pragma unroll
            for (int nt = 0; nt < 8; nt++)
                #pragma unroll
                for (int j = 0; j < 4; j++) S[mt][nt][j] = 0.f;

        #pragma unroll
        for (int ks = 0; ks < 12; ks++) {
            const int kb = ks * 16 + tg * 2;
            uint32_t a[2][4];
            #pragma unroll
            for (int mt = 0; mt < 2; mt++) {
                const int r = wrow + mt * 16 + g;
                a[mt][0] = *(const uint32_t*)&Qs[r       * QPITCH + kb];
                a[mt][1] = *(const uint32_t*)&Qs[(r + 8) * QPITCH + kb];
                a[mt][2] = *(const uint32_t*)&Qs[r       * QPITCH + kb + 8];
                a[mt][3] = *(const uint32_t*)&Qs[(r + 8) * QPITCH + kb + 8];
            }
            #pragma unroll
            for (int nt = 0; nt < 8; nt++) {
                uint32_t bb[2];
                bb[0] = *(const uint32_t*)&Ks[(nt * 8 + g) * QPITCH + kb];
                bb[1] = *(const uint32_t*)&Ks[(nt * 8 + g) * QPITCH + kb + 8];
                mma16816(S[0][nt], a[0], bb);
                mma16816(S[1][nt], a[1], bb);
            }
        }

        // scale + mask + online softmax per mt
        #pragma unroll
        for (int mt = 0; mt < 2; mt++) {
            #pragma unroll
            for (int nt = 0; nt < 8; nt++) {
                const int key = j0 + nt * 8 + tg * 2;
                const bool v0 = key < NTOK, v1 = key + 1 < NTOK;
                S[mt][nt][0] = v0 ? S[mt][nt][0] * 0.125f : -1e30f;
                S[mt][nt][1] = v1 ? S[mt][nt][1] * 0.125f : -1e30f;
                S[mt][nt][2] = v0 ? S[mt][nt][2] * 0.125f : -1e30f;
                S[mt][nt][3] = v1 ? S[mt][nt][3] * 0.125f : -1e30f;
            }

            float t0 = -1e30f, t1 = -1e30f;
            #pragma unroll
            for (int nt = 0; nt < 8; nt++) {
                t0 = fmaxf(t0, fmaxf(S[mt][nt][0], S[mt][nt][1]));
                t1 = fmaxf(t1, fmaxf(S[mt][nt][2], S[mt][nt][3]));
            }
            t0 = fmaxf(t0, __shfl_xor_sync(0xffffffffu, t0, 1));
            t0 = fmaxf(t0, __shfl_xor_sync(0xffffffffu, t0, 2));
            t1 = fmaxf(t1, __shfl_xor_sync(0xffffffffu, t1, 1));
            t1 = fmaxf(t1, __shfl_xor_sync(0xffffffffu, t1, 2));

            const float mn0 = fmaxf(mrow[mt][0], t0), mn1 = fmaxf(mrow[mt][1], t1);
            const float al0 = __expf(mrow[mt][0] - mn0), al1 = __expf(mrow[mt][1] - mn1);
            mrow[mt][0] = mn0; mrow[mt][1] = mn1;

            float rs0 = 0.f, rs1 = 0.f;
            #pragma unroll
            for (int nt = 0; nt < 8; nt++) {
                S[mt][nt][0] = __expf(S[mt][nt][0] - mn0);
                S[mt][nt][1] = __expf(S[mt][nt][1] - mn0);
                S[mt][nt][2] = __expf(S[mt][nt][2] - mn1);
                S[mt][nt][3] = __expf(S[mt][nt][3] - mn1);
                rs0 += S[mt][nt][0] + S[mt][nt][1];
                rs1 += S[mt][nt][2] + S[mt][nt][3];
            }
            rs0 += __shfl_xor_sync(0xffffffffu, rs0, 1);
            rs0 += __shfl_xor_sync(0xffffffffu, rs0, 2);
            rs1 += __shfl_xor_sync(0xffffffffu, rs1, 1);
            rs1 += __shfl_xor_sync(0xffffffffu, rs1, 2);
            lrow[mt][0] = lrow[mt][0] * al0 + rs0;
            lrow[mt][1] = lrow[mt][1] * al1 + rs1;

            #pragma unroll
            for (int nt = 0; nt < 8; nt++) {
                O[mt][nt][0] *= al0; O[mt][nt][1] *= al0;
                O[mt][nt][2] *= al1; O[mt][nt][3] *= al1;
            }
        }

        // pack P into A-fragments (hi + lo) for both mt
        uint32_t ph[2][4][4], pl[2][4][4];
        #pragma unroll
        for (int mt = 0; mt < 2; mt++) {
            #pragma unroll
            for (int ks = 0; ks < 4; ks++) {
                pack_hilo(S[mt][2*ks][0],   S[mt][2*ks][1],   ph[mt][ks][0], pl[mt][ks][0]);
                pack_hilo(S[mt][2*ks][2],   S[mt][2*ks][3],   ph[mt][ks][1], pl[mt][ks][1]);
                pack_hilo(S[mt][2*ks+1][0], S[mt][2*ks+1][1], ph[mt][ks][2], pl[mt][ks][2]);
                pack_hilo(S[mt][2*ks+1][2], S[mt][2*ks+1][3], ph[mt][ks][3], pl[mt][ks][3]);
            }
        }

        // ---- PV: O += P @ V (3-term split), V fragments reused across mt ----
        #pragma unroll
        for (int ks = 0; ks < 4; ks++) {
            const int kb = ks * 16 + tg * 2;
            #pragma unroll
            for (int nt = 0; nt < 8; nt++) {
                uint32_t bh2[2], bl2[2];
                bh2[0] = *(const uint32_t*)&Vh[(nt * 8 + g) * VPITCH + kb];
                bh2[1] = *(const uint32_t*)&Vh[(nt * 8 + g) * VPITCH + kb + 8];
                bl2[0] = *(const uint32_t*)&Vl[(nt * 8 + g) * VPITCH + kb];
                bl2[1] = *(const uint32_t*)&Vl[(nt * 8 + g) * VPITCH + kb + 8];
                #pragma unroll
                for (int mt = 0; mt < 2; mt++) {
                    mma16816(O[mt][nt], ph[mt][ks], bh2);
                    mma16816(O[mt][nt], ph[mt][ks], bl2);
                    mma16816(O[mt][nt], pl[mt][ks], bh2);
                }
            }
        }
    }

    // epilogue
    const int b = bh / H_, h = bh - b * H_;
    #pragma unroll
    for (int mt = 0; mt < 2; mt++) {
        const float inv0 = 1.f / lrow[mt][0], inv1 = 1.f / lrow[mt][1];
        const int row0 = b * NTOK + TTXT + q0 + wrow + mt * 16 + g;
        const int row1 = row0 + 8;
        #pragma unroll
        for (int nt = 0; nt < 8; nt++) {
            const int c = h * HD + nt * 8 + tg * 2;
            store_split3(row0, c,     O[mt][nt][0] * inv0);
            store_split3(row0, c + 1, O[mt][nt][1] * inv0);
            store_split3(row1, c,     O[mt][nt][2] * inv1);
            store_split3(row1, c + 1, O[mt][nt][3] * inv1);
        }
    }
}

// ---------------- launch ----------------
extern "C" void kernel_launch(void* const* d_in, const int* in_sizes, int n_in,
                              void* d_out, int out_size)
{
    const float* x      = (const float*)d_in[0];
    const float* qkv_w  = (const float*)d_in[1];
    const float* proj_w = (const float*)d_in[2];
    const float* proj_b = (const float*)d_in[3];
    float* out = (float*)d_out;

    cudaFuncSetAttribute(img_attn_mma_kernel,
                         cudaFuncAttributeMaxDynamicSharedMemorySize, IMG_SMEM2);

    split_x_kernel <<<(MPAD*CDIM + 255)/256, 256>>>(x);
    split_w1_kernel<<<(NQKV*CDIM + 255)/256, 256>>>(qkv_w);
    split_w2_kernel<<<(CDIM*CDIM + 255)/256, 256>>>(proj_w);

    qkv_gemm_kernel<<<dim3(NQKV/128, MPAD/128), 128>>>();

    text_attn_kernel<<<B_*H_, 64>>>();
    img_attn_mma_kernel<<<dim3(SIMG/128, B_*H_), 128, IMG_SMEM2>>>();

    proj_gemm_kernel<<<dim3(CDIM/128, MPAD/128), 128>>>(proj_b, out);
}

// round 8
// speedup vs baseline: 3.6495x; 1.0559x over previous
#include <cuda_runtime.h>
#include <cuda_bf16.h>
#include <cstdint>

// ---------------- problem constants ----------------
#define B_    8
#define TTXT  40
#define SIMG  1024
#define NTOK  1064
#define CDIM  768
#define H_    12
#define HD    64
#define MROWS (B_*NTOK)       // 8512
#define MPAD  8576            // 67*128
#define K3    (3*CDIM)        // 2304
#define NQKV  (3*CDIM)        // 2304

// ---------------- device scratch (referenced ONLY from device code) ----------------
__device__ float g_q [B_*H_*NTOK*HD];
__device__ float g_k [B_*H_*NTOK*HD];
__device__ float g_v [B_*H_*NTOK*HD];

__device__ __align__(16) __nv_bfloat16 gxc [MPAD*K3];
__device__ __align__(16) __nv_bfloat16 gw1c[NQKV*K3];
__device__ __align__(16) __nv_bfloat16 gw2c[CDIM*K3];
__device__ __align__(16) __nv_bfloat16 gaoc[MPAD*K3];

__device__ __align__(16) __nv_bfloat16 g_qc [B_*H_*NTOK*192];  // [bh][n][hi|hi|lo]
__device__ __align__(16) __nv_bfloat16 g_kc [B_*H_*NTOK*192];  // [bh][n][hi|lo|hi]
__device__ __align__(16) __nv_bfloat16 g_vht[B_*H_*HD*NTOK];   // V^T hi: [bh][e][n]
__device__ __align__(16) __nv_bfloat16 g_vlt[B_*H_*HD*NTOK];   // V^T lo

// ---------------- split/concat kernels ----------------
__global__ __launch_bounds__(256) void split_x_kernel(const float* __restrict__ src)
{
    int i = blockIdx.x * 256 + threadIdx.x;
    if (i >= MPAD * CDIM) return;
    int row = i / CDIM, c = i - row * CDIM;
    float f = (row < MROWS) ? src[(size_t)row * CDIM + c] : 0.f;
    __nv_bfloat16 h = __float2bfloat16(f);
    __nv_bfloat16 l = __float2bfloat16(f - __bfloat162float(h));
    size_t base = (size_t)row * K3 + c;
    gxc[base]          = h;
    gxc[base + CDIM]   = h;
    gxc[base + 2*CDIM] = l;
}

__global__ __launch_bounds__(256) void split_w1_kernel(const float* __restrict__ src)
{
    int i = blockIdx.x * 256 + threadIdx.x;
    if (i >= NQKV * CDIM) return;
    int row = i / CDIM, c = i - row * CDIM;
    float f = src[(size_t)row * CDIM + c];
    __nv_bfloat16 h = __float2bfloat16(f);
    __nv_bfloat16 l = __float2bfloat16(f - __bfloat162float(h));
    size_t base = (size_t)row * K3 + c;
    gw1c[base]          = h;
    gw1c[base + CDIM]   = l;
    gw1c[base + 2*CDIM] = h;
}

__global__ __launch_bounds__(256) void split_w2_kernel(const float* __restrict__ src)
{
    int i = blockIdx.x * 256 + threadIdx.x;
    if (i >= CDIM * CDIM) return;
    int row = i / CDIM, c = i - row * CDIM;
    float f = src[(size_t)row * CDIM + c];
    __nv_bfloat16 h = __float2bfloat16(f);
    __nv_bfloat16 l = __float2bfloat16(f - __bfloat162float(h));
    size_t base = (size_t)row * K3 + c;
    gw2c[base]          = h;
    gw2c[base + CDIM]   = l;
    gw2c[base + 2*CDIM] = h;
}

// ---------------- warp mma + ldmatrix ----------------
__device__ __forceinline__ void mma16816(float* d, const uint32_t* a, const uint32_t* b)
{
    asm volatile(
        "mma.sync.aligned.m16n8k16.row.col.f32.bf16.bf16.f32 "
        "{%0,%1,%2,%3}, {%4,%5,%6,%7}, {%8,%9}, {%0,%1,%2,%3};"
        : "+f"(d[0]), "+f"(d[1]), "+f"(d[2]), "+f"(d[3])
        : "r"(a[0]), "r"(a[1]), "r"(a[2]), "r"(a[3]), "r"(b[0]), "r"(b[1]));
}

__device__ __forceinline__ void ldsm4(uint32_t* r, uint32_t addr)
{
    asm volatile("ldmatrix.sync.aligned.m8n8.x4.shared.b16 {%0,%1,%2,%3}, [%4];"
        : "=r"(r[0]), "=r"(r[1]), "=r"(r[2]), "=r"(r[3]) : "r"(addr));
}

// D[128,128] = A[rows@m0][K3] @ B[rows@n0][K3]^T, fp32 accum.
// 128 threads, 4 warps 2x2, warp tile 64x64 (mt4 x nt8). Fragment feeds via ldmatrix.
__device__ __forceinline__ void gemm_main(const __nv_bfloat16* __restrict__ A,
                                          const __nv_bfloat16* __restrict__ B,
                                          int m0, int n0, float acc[4][8][4])
{
    __shared__ __align__(16) __nv_bfloat16 As[2][128][40];
    __shared__ __align__(16) __nv_bfloat16 Bs[2][128][40];

    const int tid  = threadIdx.x;
    const int lane = tid & 31, wid = tid >> 5;
    const int wm = (wid & 1) * 64;
    const int wn = (wid >> 1) * 64;

    const int lr = tid >> 2;          // 0..31
    const int lk = (tid & 3) * 8;     // 0,8,16,24

    const __nv_bfloat16* Ap = A + (size_t)(m0 + lr) * K3 + lk;
    const __nv_bfloat16* Bp = B + (size_t)(n0 + lr) * K3 + lk;

    // ldmatrix lane-address bases (buffer 0)
    const uint32_t BUFB = 128 * 40 * 2;   // bytes per As/Bs buffer
    const uint32_t aBase = (uint32_t)__cvta_generic_to_shared(
        &As[0][wm + (lane & 15)][(lane >> 4) * 8]);
    const uint32_t bBase = (uint32_t)__cvta_generic_to_shared(
        &Bs[0][wn + ((lane >> 4) * 8) + (lane & 7)][((lane >> 3) & 1) * 8]);

    uint4 ra[4], rb[4];

    #pragma unroll
    for (int i = 0; i < 4; i++) {
        ra[i] = *(const uint4*)(Ap + (size_t)(32*i) * K3);
        rb[i] = *(const uint4*)(Bp + (size_t)(32*i) * K3);
    }
    #pragma unroll
    for (int i = 0; i < 4; i++) {
        *(uint4*)&As[0][lr + 32*i][lk] = ra[i];
        *(uint4*)&Bs[0][lr + 32*i][lk] = rb[i];
    }
    __syncthreads();

    const int NKI = K3 / 32;          // 72
    for (int t = 0; t < NKI; t++) {
        const int buf = t & 1;
        const uint32_t aB = aBase + buf * BUFB;
        const uint32_t bB = bBase + buf * BUFB;
        if (t + 1 < NKI) {
            const size_t o = (size_t)(t + 1) * 32;
            #pragma unroll
            for (int i = 0; i < 4; i++) {
                ra[i] = *(const uint4*)(Ap + o + (size_t)(32*i) * K3);
                rb[i] = *(const uint4*)(Bp + o + (size_t)(32*i) * K3);
            }
        }
        #pragma unroll
        for (int ks = 0; ks < 2; ks++) {
            uint32_t af[4][4], bfr[8][2];
            #pragma unroll
            for (int mt = 0; mt < 4; mt++)
                ldsm4(af[mt], aB + mt * (16 * 80) + ks * 32);
            #pragma unroll
            for (int np = 0; np < 4; np++) {
                uint32_t tmp[4];
                ldsm4(tmp, bB + np * (16 * 80) + ks * 32);
                bfr[2*np][0]   = tmp[0];
                bfr[2*np][1]   = tmp[1];
                bfr[2*np+1][0] = tmp[2];
                bfr[2*np+1][1] = tmp[3];
            }
            #pragma unroll
            for (int mt = 0; mt < 4; mt++)
                #pragma unroll
                for (int nt = 0; nt < 8; nt++)
                    mma16816(acc[mt][nt], af[mt], bfr[nt]);
        }
        if (t + 1 < NKI) {
            const int nb = buf ^ 1;
            #pragma unroll
            for (int i = 0; i < 4; i++) {
                *(uint4*)&As[nb][lr + 32*i][lk] = ra[i];
                *(uint4*)&Bs[nb][lr + 32*i][lk] = rb[i];
            }
        }
        __syncthreads();
    }
}

// ---------------- QKV GEMM: epilogue writes attention-ready layouts ----------------
__global__ __launch_bounds__(128) void qkv_gemm_kernel()
{
    const int n0 = blockIdx.x * 128;
    const int m0 = blockIdx.y * 128;

    float acc[4][8][4] = {};
    gemm_main(gxc, gw1c, m0, n0, acc);

    const int lane = threadIdx.x & 31, wid = threadIdx.x >> 5;
    const int wm = (wid & 1) * 64, wn = (wid >> 1) * 64;
    const int g = lane >> 2, tg = lane & 3;

    const int s3    = n0 / CDIM;
    const int nrem0 = n0 - s3 * CDIM;

    #pragma unroll
    for (int mt = 0; mt < 4; mt++) {
        #pragma unroll
        for (int nt = 0; nt < 8; nt++) {
            const int col = nrem0 + wn + nt * 8 + tg * 2;
            const int hh = col >> 6, e = col & 63;
            #pragma unroll
            for (int rr = 0; rr < 2; rr++) {
                const int mm = m0 + wm + mt * 16 + g + rr * 8;
                if (mm >= MROWS) continue;
                const int b = mm / NTOK;
                const int n = mm - b * NTOK;
                const size_t idx = (size_t)(b * H_ + hh) * NTOK + n;
                const float v0 = acc[mt][nt][rr * 2 + 0];
                const float v1 = acc[mt][nt][rr * 2 + 1];
                const __nv_bfloat16 h0 = __float2bfloat16(v0);
                const __nv_bfloat16 h1 = __float2bfloat16(v1);
                const __nv_bfloat16 l0 = __float2bfloat16(v0 - __bfloat162float(h0));
                const __nv_bfloat16 l1 = __float2bfloat16(v1 - __bfloat162float(h1));
                if (s3 == 0) {
                    __nv_bfloat16* qd = g_qc + idx * 192 + e;
                    qd[0]   = h0; qd[1]   = h1;
                    qd[64]  = h0; qd[65]  = h1;
                    qd[128] = l0; qd[129] = l1;
                    if (n < TTXT) { g_q[idx*HD + e] = v0; g_q[idx*HD + e + 1] = v1; }
                } else if (s3 == 1) {
                    __nv_bfloat16* kd = g_kc + idx * 192 + e;
                    kd[0]   = h0; kd[1]   = h1;
                    kd[64]  = l0; kd[65]  = l1;
                    kd[128] = h0; kd[129] = h1;
                    if (n < TTXT) { g_k[idx*HD + e] = v0; g_k[idx*HD + e + 1] = v1; }
                } else {
                    const size_t vi = ((size_t)(b * H_ + hh) * HD + e) * NTOK + n;
                    g_vht[vi]        = h0;
                    g_vht[vi + NTOK] = h1;
                    g_vlt[vi]        = l0;
                    g_vlt[vi + NTOK] = l1;
                    if (n < TTXT) { g_v[idx*HD + e] = v0; g_v[idx*HD + e + 1] = v1; }
                }
            }
        }
    }
}

// ---------------- proj GEMM kernel ----------------
__global__ __launch_bounds__(128) void proj_gemm_kernel(const float* __restrict__ bias,
                                                        float* __restrict__ out)
{
    const int n0 = blockIdx.x * 128;
    const int m0 = blockIdx.y * 128;

    float acc[4][8][4] = {};
    gemm_main(gaoc, gw2c, m0, n0, acc);

    const int lane = threadIdx.x & 31, wid = threadIdx.x >> 5;
    const int wm = (wid & 1) * 64, wn = (wid >> 1) * 64;
    const int g = lane >> 2, tg = lane & 3;

    #pragma unroll
    for (int mt = 0; mt < 4; mt++) {
        #pragma unroll
        for (int nt = 0; nt < 8; nt++) {
            const int d = n0 + wn + nt * 8 + tg * 2;
            const float b0 = bias[d], b1 = bias[d + 1];
            #pragma unroll
            for (int rr = 0; rr < 2; rr++) {
                const int m = m0 + wm + mt * 16 + g + rr * 8;
                if (m >= MROWS) continue;
                out[(size_t)m * CDIM + d]     = acc[mt][nt][rr * 2 + 0] + b0;
                out[(size_t)m * CDIM + d + 1] = acc[mt][nt][rr * 2 + 1] + b1;
            }
        }
    }
}

// ---------------- gaoc split-store (A-side hi|hi|lo) ----------------
__device__ __forceinline__ void store_split3(int row, int c, float v)
{
    __nv_bfloat16 h = __float2bfloat16(v);
    __nv_bfloat16 l = __float2bfloat16(v - __bfloat162float(h));
    size_t base = (size_t)row * K3 + c;
    gaoc[base]          = h;
    gaoc[base + CDIM]   = h;
    gaoc[base + 2*CDIM] = l;
}

// ---------------- text attention (fp32, tiny) ----------------
__global__ __launch_bounds__(64) void text_attn_kernel()
{
    const int bh = blockIdx.x;
    const int b = bh / H_;
    const int h = bh - b * H_;

    __shared__ float Kt[TTXT][HD];
    __shared__ float Vt[TTXT][HD];

    const size_t base = (size_t)(b*H_ + h) * NTOK * HD;
    const float* kbase = g_k + base;
    const float* vbase = g_v + base;

    const int tid = threadIdx.x;
    for (int i = tid; i < TTXT*HD; i += 64) {
        Kt[i / HD][i % HD] = kbase[i];
        Vt[i / HD][i % HD] = vbase[i];
    }
    __syncthreads();

    if (tid < TTXT) {
        const float* qrow = g_q + base + (size_t)tid * HD;
        float qv[HD];
        #pragma unroll
        for (int e = 0; e < HD; e++) qv[e] = qrow[e];

        float sc[TTXT];
        float mx = -1e30f;
        #pragma unroll 4
        for (int s = 0; s < TTXT; s++) {
            float d = 0.f;
            #pragma unroll
            for (int e = 0; e < HD; e++) d += qv[e] * Kt[s][e];
            d *= 0.125f;
            sc[s] = d;
            mx = fmaxf(mx, d);
        }
        float sum = 0.f;
        #pragma unroll
        for (int s = 0; s < TTXT; s++) { sc[s] = __expf(sc[s] - mx); sum += sc[s]; }
        float inv = 1.f / sum;

        const int row = b * NTOK + tid;
        #pragma unroll 4
        for (int e = 0; e < HD; e++) {
            float a = 0.f;
            #pragma unroll
            for (int s = 0; s < TTXT; s++) a += sc[s] * Vt[s][e];
            store_split3(row, h * HD + e, a * inv);
        }
    }
}

// ---------------- image attention: mma flash kernel (128-query blocks) ----------------
#define QPITCH 200
#define VPITCH 72
#define OFF_K  51200
#define OFF_VH 76800
#define OFF_VL 86016
#define IMG_SMEM2 95232

__device__ __forceinline__ void pack_hilo(float x, float y, uint32_t& hi, uint32_t& lo)
{
    __nv_bfloat162 h = __floats2bfloat162_rn(x, y);
    float hx = __bfloat162float(h.x), hy = __bfloat162float(h.y);
    __nv_bfloat162 l = __floats2bfloat162_rn(x - hx, y - hy);
    hi = *(uint32_t*)&h;
    lo = *(uint32_t*)&l;
}

__global__ __launch_bounds__(128) void img_attn_mma_kernel()
{
    extern __shared__ char smx[];
    __nv_bfloat16* Qs = (__nv_bfloat16*)(smx);            // [128][200]
    __nv_bfloat16* Ks = (__nv_bfloat16*)(smx + OFF_K);    // [64][200]
    __nv_bfloat16* Vh = (__nv_bfloat16*)(smx + OFF_VH);   // [64][72]
    __nv_bfloat16* Vl = (__nv_bfloat16*)(smx + OFF_VL);   // [64][72]

    const int bh = blockIdx.y;
    const int q0 = blockIdx.x * 128;
    const int tid = threadIdx.x;
    const int lane = tid & 31, wid = tid >> 5;
    const int g = lane >> 2, tg = lane & 3;
    const int wrow = wid * 32;            // 32 query rows per warp (mt=2)

    // ldmatrix lane-address bases
    const uint32_t qBase = (uint32_t)__cvta_generic_to_shared(
        Qs + (wrow + (lane & 15)) * QPITCH + (lane >> 4) * 8);
    const uint32_t kBase = (uint32_t)__cvta_generic_to_shared(
        Ks + (((lane >> 4) * 8) + (lane & 7)) * QPITCH + ((lane >> 3) & 1) * 8);
    const uint32_t vhBase = (uint32_t)__cvta_generic_to_shared(
        Vh + (((lane >> 4) * 8) + (lane & 7)) * VPITCH + ((lane >> 3) & 1) * 8);
    const uint32_t vlBase = (uint32_t)__cvta_generic_to_shared(
        Vl + (((lane >> 4) * 8) + (lane & 7)) * VPITCH + ((lane >> 3) & 1) * 8);

    // load Q tile (128 rows x 192)
    {
        const __nv_bfloat16* qsrc = g_qc + ((size_t)bh * NTOK + TTXT + q0) * 192;
        for (int u = tid; u < 128 * 24; u += 128) {
            int r = u / 24, o = (u % 24) * 8;
            *(uint4*)&Qs[r * QPITCH + o] = *(const uint4*)(qsrc + (size_t)r * 192 + o);
        }
    }

    float mrow[2][2], lrow[2][2];
    #pragma unroll
    for (int mt = 0; mt < 2; mt++) { mrow[mt][0] = mrow[mt][1] = -1e30f; lrow[mt][0] = lrow[mt][1] = 0.f; }

    float O[2][8][4];
    #pragma unroll
    for (int mt = 0; mt < 2; mt++)
        #pragma unroll
        for (int nt = 0; nt < 8; nt++)
            #pragma unroll
            for (int j = 0; j < 4; j++) O[mt][nt][j] = 0.f;

    const __nv_bfloat16* kcb = g_kc + (size_t)bh * NTOK * 192;
    const __nv_bfloat16* vhb = g_vht + (size_t)bh * HD * NTOK;
    const __nv_bfloat16* vlb = g_vlt + (size_t)bh * HD * NTOK;

    for (int t = 0; t < 17; t++) {
        const int j0 = t * 64;
        __syncthreads();

        // K tile: 64 keys x 192
        for (int u = tid; u < 64 * 24; u += 128) {
            int r = u / 24, o = (u % 24) * 8;
            uint4 val = make_uint4(0u, 0u, 0u, 0u);
            if (j0 + r < NTOK)
                val = *(const uint4*)(kcb + (size_t)(j0 + r) * 192 + o);
            *(uint4*)&Ks[r * QPITCH + o] = val;
        }
        // V^T tiles: 64 dims x 64 keys
        for (int u = tid; u < 64 * 8; u += 128) {
            int e = u >> 3, o = (u & 7) * 8;
            uint4 vhv = make_uint4(0u, 0u, 0u, 0u);
            uint4 vlv = make_uint4(0u, 0u, 0u, 0u);
            if (j0 + o + 7 < NTOK) {
                vhv = *(const uint4*)(vhb + (size_t)e * NTOK + j0 + o);
                vlv = *(const uint4*)(vlb + (size_t)e * NTOK + j0 + o);
            }
            *(uint4*)&Vh[e * VPITCH + o] = vhv;
            *(uint4*)&Vl[e * VPITCH + o] = vlv;
        }
        __syncthreads();

        // ---- scores: S[2][8][4] = 32 rows x 64 keys per warp ----
        float S[2][8][4];
        #pragma unroll
        for (int mt = 0; mt < 2; mt++)
            #pragma unroll
            for (int nt = 0; nt < 8; nt++)
                #pragma unroll
                for (int j = 0; j < 4; j++) S[mt][nt][j] = 0.f;

        #pragma unroll
        for (int ks = 0; ks < 12; ks++) {
            uint32_t a[2][4];
            ldsm4(a[0], qBase + ks * 32);
            ldsm4(a[1], qBase + 16 * (QPITCH * 2) + ks * 32);
            uint32_t bfr[8][2];
            #pragma unroll
            for (int np = 0; np < 4; np++) {
                uint32_t tmp[4];
                ldsm4(tmp, kBase + np * (16 * QPITCH * 2) + ks * 32);
                bfr[2*np][0]   = tmp[0];
                bfr[2*np][1]   = tmp[1];
                bfr[2*np+1][0] = tmp[2];
                bfr[2*np+1][1] = tmp[3];
            }
            #pragma unroll
            for (int nt = 0; nt < 8; nt++) {
                mma16816(S[0][nt], a[0], bfr[nt]);
                mma16816(S[1][nt], a[1], bfr[nt]);
            }
        }

        // scale + mask + online softmax per mt
        #pragma unroll
        for (int mt = 0; mt < 2; mt++) {
            #pragma unroll
            for (int nt = 0; nt < 8; nt++) {
                const int key = j0 + nt * 8 + tg * 2;
                const bool v0 = key < NTOK, v1 = key + 1 < NTOK;
                S[mt][nt][0] = v0 ? S[mt][nt][0] * 0.125f : -1e30f;
                S[mt][nt][1] = v1 ? S[mt][nt][1] * 0.125f : -1e30f;
                S[mt][nt][2] = v0 ? S[mt][nt][2] * 0.125f : -1e30f;
                S[mt][nt][3] = v1 ? S[mt][nt][3] * 0.125f : -1e30f;
            }

            float t0 = -1e30f, t1 = -1e30f;
            #pragma unroll
            for (int nt = 0; nt < 8; nt++) {
                t0 = fmaxf(t0, fmaxf(S[mt][nt][0], S[mt][nt][1]));
                t1 = fmaxf(t1, fmaxf(S[mt][nt][2], S[mt][nt][3]));
            }
            t0 = fmaxf(t0, __shfl_xor_sync(0xffffffffu, t0, 1));
            t0 = fmaxf(t0, __shfl_xor_sync(0xffffffffu, t0, 2));
            t1 = fmaxf(t1, __shfl_xor_sync(0xffffffffu, t1, 1));
            t1 = fmaxf(t1, __shfl_xor_sync(0xffffffffu, t1, 2));

            const float mn0 = fmaxf(mrow[mt][0], t0), mn1 = fmaxf(mrow[mt][1], t1);
            const float al0 = __expf(mrow[mt][0] - mn0), al1 = __expf(mrow[mt][1] - mn1);
            mrow[mt][0] = mn0; mrow[mt][1] = mn1;

            float rs0 = 0.f, rs1 = 0.f;
            #pragma unroll
            for (int nt = 0; nt < 8; nt++) {
                S[mt][nt][0] = __expf(S[mt][nt][0] - mn0);
                S[mt][nt][1] = __expf(S[mt][nt][1] - mn0);
                S[mt][nt][2] = __expf(S[mt][nt][2] - mn1);
                S[mt][nt][3] = __expf(S[mt][nt][3] - mn1);
                rs0 += S[mt][nt][0] + S[mt][nt][1];
                rs1 += S[mt][nt][2] + S[mt][nt][3];
            }
            rs0 += __shfl_xor_sync(0xffffffffu, rs0, 1);
            rs0 += __shfl_xor_sync(0xffffffffu, rs0, 2);
            rs1 += __shfl_xor_sync(0xffffffffu, rs1, 1);
            rs1 += __shfl_xor_sync(0xffffffffu, rs1, 2);
            lrow[mt][0] = lrow[mt][0] * al0 + rs0;
            lrow[mt][1] = lrow[mt][1] * al1 + rs1;

            #pragma unroll
            for (int nt = 0; nt < 8; nt++) {
                O[mt][nt][0] *= al0; O[mt][nt][1] *= al0;
                O[mt][nt][2] *= al1; O[mt][nt][3] *= al1;
            }
        }

        // pack P into A-fragments (hi + lo)
        uint32_t ph[2][4][4], pl[2][4][4];
        #pragma unroll
        for (int mt = 0; mt < 2; mt++) {
            #pragma unroll
            for (int ks = 0; ks < 4; ks++) {
                pack_hilo(S[mt][2*ks][0],   S[mt][2*ks][1],   ph[mt][ks][0], pl[mt][ks][0]);
                pack_hilo(S[mt][2*ks][2],   S[mt][2*ks][3],   ph[mt][ks][1], pl[mt][ks][1]);
                pack_hilo(S[mt][2*ks+1][0], S[mt][2*ks+1][1], ph[mt][ks][2], pl[mt][ks][2]);
                pack_hilo(S[mt][2*ks+1][2], S[mt][2*ks+1][3], ph[mt][ks][3], pl[mt][ks][3]);
            }
        }

        // ---- PV: O += P @ V (3-term split) ----
        #pragma unroll
        for (int ks = 0; ks < 4; ks++) {
            uint32_t vh2[8][2], vl2[8][2];
            #pragma unroll
            for (int np = 0; np < 4; np++) {
                uint32_t th[4], tl[4];
                ldsm4(th, vhBase + np * (16 * VPITCH * 2) + ks * 32);
                ldsm4(tl, vlBase + np * (16 * VPITCH * 2) + ks * 32);
                vh2[2*np][0] = th[0]; vh2[2*np][1] = th[1];
                vh2[2*np+1][0] = th[2]; vh2[2*np+1][1] = th[3];
                vl2[2*np][0] = tl[0]; vl2[2*np][1] = tl[1];
                vl2[2*np+1][0] = tl[2]; vl2[2*np+1][1] = tl[3];
            }
            #pragma unroll
            for (int nt = 0; nt < 8; nt++) {
                #pragma unroll
                for (int mt = 0; mt < 2; mt++) {
                    mma16816(O[mt][nt], ph[mt][ks], vh2[nt]);
                    mma16816(O[mt][nt], ph[mt][ks], vl2[nt]);
                    mma16816(O[mt][nt], pl[mt][ks], vh2[nt]);
                }
            }
        }
    }

    // epilogue
    const int b = bh / H_, h = bh - b * H_;
    #pragma unroll
    for (int mt = 0; mt < 2; mt++) {
        const float inv0 = 1.f / lrow[mt][0], inv1 = 1.f / lrow[mt][1];
        const int row0 = b * NTOK + TTXT + q0 + wrow + mt * 16 + g;
        const int row1 = row0 + 8;
        #pragma unroll
        for (int nt = 0; nt < 8; nt++) {
            const int c = h * HD + nt * 8 + tg * 2;
            store_split3(row0, c,     O[mt][nt][0] * inv0);
            store_split3(row0, c + 1, O[mt][nt][1] * inv0);
            store_split3(row1, c,     O[mt][nt][2] * inv1);
            store_split3(row1, c + 1, O[mt][nt][3] * inv1);
        }
    }
}

// ---------------- launch ----------------
extern "C" void kernel_launch(void* const* d_in, const int* in_sizes, int n_in,
                              void* d_out, int out_size)
{
    const float* x      = (const float*)d_in[0];
    const float* qkv_w  = (const float*)d_in[1];
    const float* proj_w = (const float*)d_in[2];
    const float* proj_b = (const float*)d_in[3];
    float* out = (float*)d_out;

    cudaFuncSetAttribute(img_attn_mma_kernel,
                         cudaFuncAttributeMaxDynamicSharedMemorySize, IMG_SMEM2);

    split_x_kernel <<<(MPAD*CDIM + 255)/256, 256>>>(x);
    split_w1_kernel<<<(NQKV*CDIM + 255)/256, 256>>>(qkv_w);
    split_w2_kernel<<<(CDIM*CDIM + 255)/256, 256>>>(proj_w);

    qkv_gemm_kernel<<<dim3(NQKV/128, MPAD/128), 128>>>();

    text_attn_kernel<<<B_*H_, 64>>>();
    img_attn_mma_kernel<<<dim3(SIMG/128, B_*H_), 128, IMG_SMEM2>>>();

    proj_gemm_kernel<<<dim3(CDIM/128, MPAD/128), 128>>>(proj_b, out);
}

// round 9
// speedup vs baseline: 4.2407x; 1.1620x over previous
#include <cuda_runtime.h>
#include <cuda_bf16.h>
#include <cstdint>

// ---------------- problem constants ----------------
#define B_    8
#define TTXT  40
#define SIMG  1024
#define NTOK  1064
#define CDIM  768
#define H_    12
#define HD    64
#define MROWS (B_*NTOK)       // 8512
#define MPAD  8576            // 67*128
#define K3    (3*CDIM)        // 2304
#define NQKV  (3*CDIM)        // 2304

// ---------------- device scratch (referenced ONLY from device code) ----------------
__device__ float g_q [B_*H_*NTOK*HD];
__device__ float g_k [B_*H_*NTOK*HD];
__device__ float g_v [B_*H_*NTOK*HD];

__device__ __align__(16) __nv_bfloat16 gxc [MPAD*K3];
__device__ __align__(16) __nv_bfloat16 gw1c[NQKV*K3];
__device__ __align__(16) __nv_bfloat16 gw2c[CDIM*K3];
__device__ __align__(16) __nv_bfloat16 gaoc[MPAD*K3];

__device__ __align__(16) __nv_bfloat16 g_qc [B_*H_*NTOK*192];  // [bh][n][hi|hi|lo]
__device__ __align__(16) __nv_bfloat16 g_kc [B_*H_*NTOK*192];  // [bh][n][hi|lo|hi]
__device__ __align__(16) __nv_bfloat16 g_vht[B_*H_*HD*NTOK];   // V^T hi: [bh][e][n]
__device__ __align__(16) __nv_bfloat16 g_vlt[B_*H_*HD*NTOK];   // V^T lo

// ---------------- split/concat kernels ----------------
__global__ __launch_bounds__(256) void split_x_kernel(const float* __restrict__ src)
{
    int i = blockIdx.x * 256 + threadIdx.x;
    if (i >= MPAD * CDIM) return;
    int row = i / CDIM, c = i - row * CDIM;
    float f = (row < MROWS) ? src[(size_t)row * CDIM + c] : 0.f;
    __nv_bfloat16 h = __float2bfloat16(f);
    __nv_bfloat16 l = __float2bfloat16(f - __bfloat162float(h));
    size_t base = (size_t)row * K3 + c;
    gxc[base]          = h;
    gxc[base + CDIM]   = h;
    gxc[base + 2*CDIM] = l;
}

__global__ __launch_bounds__(256) void split_w1_kernel(const float* __restrict__ src)
{
    int i = blockIdx.x * 256 + threadIdx.x;
    if (i >= NQKV * CDIM) return;
    int row = i / CDIM, c = i - row * CDIM;
    float f = src[(size_t)row * CDIM + c];
    __nv_bfloat16 h = __float2bfloat16(f);
    __nv_bfloat16 l = __float2bfloat16(f - __bfloat162float(h));
    size_t base = (size_t)row * K3 + c;
    gw1c[base]          = h;
    gw1c[base + CDIM]   = l;
    gw1c[base + 2*CDIM] = h;
}

__global__ __launch_bounds__(256) void split_w2_kernel(const float* __restrict__ src)
{
    int i = blockIdx.x * 256 + threadIdx.x;
    if (i >= CDIM * CDIM) return;
    int row = i / CDIM, c = i - row * CDIM;
    float f = src[(size_t)row * CDIM + c];
    __nv_bfloat16 h = __float2bfloat16(f);
    __nv_bfloat16 l = __float2bfloat16(f - __bfloat162float(h));
    size_t base = (size_t)row * K3 + c;
    gw2c[base]          = h;
    gw2c[base + CDIM]   = l;
    gw2c[base + 2*CDIM] = h;
}

// ---------------- warp mma + ldmatrix + cp.async ----------------
__device__ __forceinline__ void mma16816(float* d, const uint32_t* a, const uint32_t* b)
{
    asm volatile(
        "mma.sync.aligned.m16n8k16.row.col.f32.bf16.bf16.f32 "
        "{%0,%1,%2,%3}, {%4,%5,%6,%7}, {%8,%9}, {%0,%1,%2,%3};"
        : "+f"(d[0]), "+f"(d[1]), "+f"(d[2]), "+f"(d[3])
        : "r"(a[0]), "r"(a[1]), "r"(a[2]), "r"(a[3]), "r"(b[0]), "r"(b[1]));
}

__device__ __forceinline__ void ldsm4(uint32_t* r, uint32_t addr)
{
    asm volatile("ldmatrix.sync.aligned.m8n8.x4.shared.b16 {%0,%1,%2,%3}, [%4];"
        : "=r"(r[0]), "=r"(r[1]), "=r"(r[2]), "=r"(r[3]) : "r"(addr));
}

__device__ __forceinline__ void cpa16(uint32_t dst, const void* src)
{
    asm volatile("cp.async.cg.shared.global [%0], [%1], 16;" :: "r"(dst), "l"(src));
}
#define CP_COMMIT() asm volatile("cp.async.commit_group;" ::: "memory")
#define CP_WAIT(n)  asm volatile("cp.async.wait_group %0;" :: "n"(n) : "memory")

// D[128,128] = A[rows@m0][K3] @ B[rows@n0][K3]^T, fp32 accum.
// 128 threads, 4 warps 2x2, warp tile 64x64. 3-stage cp.async pipeline.
// dynamic smem: As 3 stages [128][40] then Bs 3 stages [128][40] (bf16).
#define GSTG  10240                  // bytes per matrix per stage (128*40*2)
#define GEMM_SMEM (6 * GSTG)         // 61440

__device__ __forceinline__ void gemm_main(const __nv_bfloat16* __restrict__ A,
                                          const __nv_bfloat16* __restrict__ B,
                                          int m0, int n0, float acc[4][8][4],
                                          char* gsm)
{
    const int tid  = threadIdx.x;
    const int lane = tid & 31, wid = tid >> 5;
    const int wm = (wid & 1) * 64;
    const int wn = (wid >> 1) * 64;

    const int lr = tid >> 2;          // 0..31
    const int lkb = (tid & 3) * 16;   // byte col offset: 0,16,32,48

    const uint32_t smA = (uint32_t)__cvta_generic_to_shared(gsm);
    const uint32_t smB = smA + 3 * GSTG;

    const char* Ap = (const char*)(A + (size_t)(m0 + lr) * K3) + lkb;
    const char* Bp = (const char*)(B + (size_t)(n0 + lr) * K3) + lkb;

    // per-thread cp.async destination base (stage 0)
    const uint32_t dA = smA + lr * 80 + lkb;
    const uint32_t dB = smB + lr * 80 + lkb;

    // ldmatrix lane-address bases (stage 0)
    const uint32_t aBase = smA + (wm + (lane & 15)) * 80 + (lane >> 4) * 16;
    const uint32_t bBase = smB + (wn + ((lane >> 4) * 8) + (lane & 7)) * 80
                               + ((lane >> 3) & 1) * 16;

    const int NKI = K3 / 32;          // 72

    // prologue: stages 0,1
    #pragma unroll
    for (int p = 0; p < 2; p++) {
        const size_t o = (size_t)p * 64;          // 32 cols * 2B
        #pragma unroll
        for (int i = 0; i < 4; i++) {
            cpa16(dA + p * GSTG + (32*i) * 80, Ap + o + (size_t)(32*i) * K3 * 2);
            cpa16(dB + p * GSTG + (32*i) * 80, Bp + o + (size_t)(32*i) * K3 * 2);
        }
        CP_COMMIT();
    }

    for (int t = 0; t < NKI; t++) {
        if (t + 2 < NKI) {
            const int s = (t + 2) % 3;
            const size_t o = (size_t)(t + 2) * 64;
            #pragma unroll
            for (int i = 0; i < 4; i++) {
                cpa16(dA + s * GSTG + (32*i) * 80, Ap + o + (size_t)(32*i) * K3 * 2);
                cpa16(dB + s * GSTG + (32*i) * 80, Bp + o + (size_t)(32*i) * K3 * 2);
            }
            CP_COMMIT();
            CP_WAIT(2);
        } else if (t + 1 < NKI) {
            CP_WAIT(1);
        } else {
            CP_WAIT(0);
        }
        __syncthreads();

        const uint32_t aB = aBase + (t % 3) * GSTG;
        const uint32_t bB = bBase + (t % 3) * GSTG;
        #pragma unroll
        for (int ks = 0; ks < 2; ks++) {
            uint32_t af[4][4], bfr[8][2];
            #pragma unroll
            for (int mt = 0; mt < 4; mt++)
                ldsm4(af[mt], aB + mt * (16 * 80) + ks * 32);
            #pragma unroll
            for (int np = 0; np < 4; np++) {
                uint32_t tmp[4];
                ldsm4(tmp, bB + np * (16 * 80) + ks * 32);
                bfr[2*np][0]   = tmp[0];
                bfr[2*np][1]   = tmp[1];
                bfr[2*np+1][0] = tmp[2];
                bfr[2*np+1][1] = tmp[3];
            }
            #pragma unroll
            for (int mt = 0; mt < 4; mt++)
                #pragma unroll
                for (int nt = 0; nt < 8; nt++)
                    mma16816(acc[mt][nt], af[mt], bfr[nt]);
        }
        __syncthreads();
    }
}

// ---------------- QKV GEMM: epilogue writes attention-ready layouts ----------------
__global__ __launch_bounds__(128) void qkv_gemm_kernel()
{
    extern __shared__ char gsm[];
    const int n0 = blockIdx.x * 128;
    const int m0 = blockIdx.y * 128;

    float acc[4][8][4] = {};
    gemm_main(gxc, gw1c, m0, n0, acc, gsm);

    const int lane = threadIdx.x & 31, wid = threadIdx.x >> 5;
    const int wm = (wid & 1) * 64, wn = (wid >> 1) * 64;
    const int g = lane >> 2, tg = lane & 3;

    const int s3    = n0 / CDIM;
    const int nrem0 = n0 - s3 * CDIM;

    #pragma unroll
    for (int mt = 0; mt < 4; mt++) {
        #pragma unroll
        for (int nt = 0; nt < 8; nt++) {
            const int col = nrem0 + wn + nt * 8 + tg * 2;
            const int hh = col >> 6, e = col & 63;
            #pragma unroll
            for (int rr = 0; rr < 2; rr++) {
                const int mm = m0 + wm + mt * 16 + g + rr * 8;
                if (mm >= MROWS) continue;
                const int b = mm / NTOK;
                const int n = mm - b * NTOK;
                const size_t idx = (size_t)(b * H_ + hh) * NTOK + n;
                const float v0 = acc[mt][nt][rr * 2 + 0];
                const float v1 = acc[mt][nt][rr * 2 + 1];
                const __nv_bfloat16 h0 = __float2bfloat16(v0);
                const __nv_bfloat16 h1 = __float2bfloat16(v1);
                const __nv_bfloat16 l0 = __float2bfloat16(v0 - __bfloat162float(h0));
                const __nv_bfloat16 l1 = __float2bfloat16(v1 - __bfloat162float(h1));
                if (s3 == 0) {
                    __nv_bfloat16* qd = g_qc + idx * 192 + e;
                    qd[0]   = h0; qd[1]   = h1;
                    qd[64]  = h0; qd[65]  = h1;
                    qd[128] = l0; qd[129] = l1;
                    if (n < TTXT) { g_q[idx*HD + e] = v0; g_q[idx*HD + e + 1] = v1; }
                } else if (s3 == 1) {
                    __nv_bfloat16* kd = g_kc + idx * 192 + e;
                    kd[0]   = h0; kd[1]   = h1;
                    kd[64]  = l0; kd[65]  = l1;
                    kd[128] = h0; kd[129] = h1;
                    if (n < TTXT) { g_k[idx*HD + e] = v0; g_k[idx*HD + e + 1] = v1; }
                } else {
                    const size_t vi = ((size_t)(b * H_ + hh) * HD + e) * NTOK + n;
                    g_vht[vi]        = h0;
                    g_vht[vi + NTOK] = h1;
                    g_vlt[vi]        = l0;
                    g_vlt[vi + NTOK] = l1;
                    if (n < TTXT) { g_v[idx*HD + e] = v0; g_v[idx*HD + e + 1] = v1; }
                }
            }
        }
    }
}

// ---------------- proj GEMM kernel ----------------
__global__ __launch_bounds__(128) void proj_gemm_kernel(const float* __restrict__ bias,
                                                        float* __restrict__ out)
{
    extern __shared__ char gsm[];
    const int n0 = blockIdx.x * 128;
    const int m0 = blockIdx.y * 128;

    float acc[4][8][4] = {};
    gemm_main(gaoc, gw2c, m0, n0, acc, gsm);

    const int lane = threadIdx.x & 31, wid = threadIdx.x >> 5;
    const int wm = (wid & 1) * 64, wn = (wid >> 1) * 64;
    const int g = lane >> 2, tg = lane & 3;

    #pragma unroll
    for (int mt = 0; mt < 4; mt++) {
        #pragma unroll
        for (int nt = 0; nt < 8; nt++) {
            const int d = n0 + wn + nt * 8 + tg * 2;
            const float b0 = bias[d], b1 = bias[d + 1];
            #pragma unroll
            for (int rr = 0; rr < 2; rr++) {
                const int m = m0 + wm + mt * 16 + g + rr * 8;
                if (m >= MROWS) continue;
                out[(size_t)m * CDIM + d]     = acc[mt][nt][rr * 2 + 0] + b0;
                out[(size_t)m * CDIM + d + 1] = acc[mt][nt][rr * 2 + 1] + b1;
            }
        }
    }
}

// ---------------- gaoc split-store (A-side hi|hi|lo) ----------------
__device__ __forceinline__ void store_split3(int row, int c, float v)
{
    __nv_bfloat16 h = __float2bfloat16(v);
    __nv_bfloat16 l = __float2bfloat16(v - __bfloat162float(h));
    size_t base = (size_t)row * K3 + c;
    gaoc[base]          = h;
    gaoc[base + CDIM]   = h;
    gaoc[base + 2*CDIM] = l;
}

// ---------------- text attention (fp32, tiny) ----------------
__global__ __launch_bounds__(64) void text_attn_kernel()
{
    const int bh = blockIdx.x;
    const int b = bh / H_;
    const int h = bh - b * H_;

    __shared__ float Kt[TTXT][HD];
    __shared__ float Vt[TTXT][HD];

    const size_t base = (size_t)(b*H_ + h) * NTOK * HD;
    const float* kbase = g_k + base;
    const float* vbase = g_v + base;

    const int tid = threadIdx.x;
    for (int i = tid; i < TTXT*HD; i += 64) {
        Kt[i / HD][i % HD] = kbase[i];
        Vt[i / HD][i % HD] = vbase[i];
    }
    __syncthreads();

    if (tid < TTXT) {
        const float* qrow = g_q + base + (size_t)tid * HD;
        float qv[HD];
        #pragma unroll
        for (int e = 0; e < HD; e++) qv[e] = qrow[e];

        float sc[TTXT];
        float mx = -1e30f;
        #pragma unroll 4
        for (int s = 0; s < TTXT; s++) {
            float d = 0.f;
            #pragma unroll
            for (int e = 0; e < HD; e++) d += qv[e] * Kt[s][e];
            d *= 0.125f;
            sc[s] = d;
            mx = fmaxf(mx, d);
        }
        float sum = 0.f;
        #pragma unroll
        for (int s = 0; s < TTXT; s++) { sc[s] = __expf(sc[s] - mx); sum += sc[s]; }
        float inv = 1.f / sum;

        const int row = b * NTOK + tid;
        #pragma unroll 4
        for (int e = 0; e < HD; e++) {
            float a = 0.f;
            #pragma unroll
            for (int s = 0; s < TTXT; s++) a += sc[s] * Vt[s][e];
            store_split3(row, h * HD + e, a * inv);
        }
    }
}

// ---------------- image attention: mma flash kernel (128-query blocks) ----------------
#define QPITCH 200
#define VPITCH 72
#define OFF_K  51200
#define OFF_VH 76800
#define OFF_VL 86016
#define IMG_SMEM2 95232

__device__ __forceinline__ void pack_hilo(float x, float y, uint32_t& hi, uint32_t& lo)
{
    __nv_bfloat162 h = __floats2bfloat162_rn(x, y);
    float hx = __bfloat162float(h.x), hy = __bfloat162float(h.y);
    __nv_bfloat162 l = __floats2bfloat162_rn(x - hx, y - hy);
    hi = *(uint32_t*)&h;
    lo = *(uint32_t*)&l;
}

__global__ __launch_bounds__(128) void img_attn_mma_kernel()
{
    extern __shared__ char smx[];
    __nv_bfloat16* Qs = (__nv_bfloat16*)(smx);            // [128][200]
    __nv_bfloat16* Ks = (__nv_bfloat16*)(smx + OFF_K);    // [64][200]
    __nv_bfloat16* Vh = (__nv_bfloat16*)(smx + OFF_VH);   // [64][72]
    __nv_bfloat16* Vl = (__nv_bfloat16*)(smx + OFF_VL);   // [64][72]

    const int bh = blockIdx.y;
    const int q0 = blockIdx.x * 128;
    const int tid = threadIdx.x;
    const int lane = tid & 31, wid = tid >> 5;
    const int g = lane >> 2, tg = lane & 3;
    const int wrow = wid * 32;            // 32 query rows per warp (mt=2)

    const uint32_t ksAddr = (uint32_t)__cvta_generic_to_shared(Ks);
    const uint32_t vhAddr = (uint32_t)__cvta_generic_to_shared(Vh);
    const uint32_t vlAddr = (uint32_t)__cvta_generic_to_shared(Vl);

    // ldmatrix lane-address bases
    const uint32_t qBase = (uint32_t)__cvta_generic_to_shared(
        Qs + (wrow + (lane & 15)) * QPITCH + (lane >> 4) * 8);
    const uint32_t kBase = ksAddr
        + ((((lane >> 4) * 8) + (lane & 7)) * QPITCH + ((lane >> 3) & 1) * 8) * 2;
    const uint32_t vhBase = vhAddr
        + ((((lane >> 4) * 8) + (lane & 7)) * VPITCH + ((lane >> 3) & 1) * 8) * 2;
    const uint32_t vlBase = vlAddr
        + ((((lane >> 4) * 8) + (lane & 7)) * VPITCH + ((lane >> 3) & 1) * 8) * 2;

    // load Q tile (128 rows x 192)
    {
        const __nv_bfloat16* qsrc = g_qc + ((size_t)bh * NTOK + TTXT + q0) * 192;
        for (int u = tid; u < 128 * 24; u += 128) {
            int r = u / 24, o = (u % 24) * 8;
            *(uint4*)&Qs[r * QPITCH + o] = *(const uint4*)(qsrc + (size_t)r * 192 + o);
        }
    }

    float mrow[2][2], lrow[2][2];
    #pragma unroll
    for (int mt = 0; mt < 2; mt++) { mrow[mt][0] = mrow[mt][1] = -1e30f; lrow[mt][0] = lrow[mt][1] = 0.f; }

    float O[2][8][4];
    #pragma unroll
    for (int mt = 0; mt < 2; mt++)
        #pragma unroll
        for (int nt = 0; nt < 8; nt++)
            #pragma unroll
            for (int j = 0; j < 4; j++) O[mt][nt][j] = 0.f;

    const __nv_bfloat16* kcb = g_kc + (size_t)bh * NTOK * 192;
    const __nv_bfloat16* vhb = g_vht + (size_t)bh * HD * NTOK;
    const __nv_bfloat16* vlb = g_vlt + (size_t)bh * HD * NTOK;

    for (int t = 0; t < 17; t++) {
        const int j0 = t * 64;
        __syncthreads();

        // K tile: 64 keys x 192 (cp.async)
        for (int u = tid; u < 64 * 24; u += 128) {
            int r = u / 24, o = (u % 24) * 8;
            if (j0 + r < NTOK)
                cpa16(ksAddr + (r * QPITCH + o) * 2, kcb + (size_t)(j0 + r) * 192 + o);
            else
                *(uint4*)&Ks[r * QPITCH + o] = make_uint4(0u, 0u, 0u, 0u);
        }
        // V^T tiles: 64 dims x 64 keys (cp.async)
        for (int u = tid; u < 64 * 8; u += 128) {
            int e = u >> 3, o = (u & 7) * 8;
            if (j0 + o + 7 < NTOK) {
                cpa16(vhAddr + (e * VPITCH + o) * 2, vhb + (size_t)e * NTOK + j0 + o);
                cpa16(vlAddr + (e * VPITCH + o) * 2, vlb + (size_t)e * NTOK + j0 + o);
            } else {
                *(uint4*)&Vh[e * VPITCH + o] = make_uint4(0u, 0u, 0u, 0u);
                *(uint4*)&Vl[e * VPITCH + o] = make_uint4(0u, 0u, 0u, 0u);
            }
        }
        CP_COMMIT();
        CP_WAIT(0);
        __syncthreads();

        // ---- scores: S[2][8][4] = 32 rows x 64 keys per warp ----
        float S[2][8][4];
        #pragma unroll
        for (int mt = 0; mt < 2; mt++)
            #pragma unroll
            for (int nt = 0; nt < 8; nt++)
                #pragma unroll
                for (int j = 0; j < 4; j++) S[mt][nt][j] = 0.f;

        #pragma unroll
        for (int ks = 0; ks < 12; ks++) {
            uint32_t a[2][4];
            ldsm4(a[0], qBase + ks * 32);
            ldsm4(a[1], qBase + 16 * (QPITCH * 2) + ks * 32);
            uint32_t bfr[8][2];
            #pragma unroll
            for (int np = 0; np < 4; np++) {
                uint32_t tmp[4];
                ldsm4(tmp, kBase + np * (16 * QPITCH * 2) + ks * 32);
                bfr[2*np][0]   = tmp[0];
                bfr[2*np][1]   = tmp[1];
                bfr[2*np+1][0] = tmp[2];
                bfr[2*np+1][1] = tmp[3];
            }
            #pragma unroll
            for (int nt = 0; nt < 8; nt++) {
                mma16816(S[0][nt], a[0], bfr[nt]);
                mma16816(S[1][nt], a[1], bfr[nt]);
            }
        }

        // scale + mask + online softmax per mt
        #pragma unroll
        for (int mt = 0; mt < 2; mt++) {
            #pragma unroll
            for (int nt = 0; nt < 8; nt++) {
                const int key = j0 + nt * 8 + tg * 2;
                const bool v0 = key < NTOK, v1 = key + 1 < NTOK;
                S[mt][nt][0] = v0 ? S[mt][nt][0] * 0.125f : -1e30f;
                S[mt][nt][1] = v1 ? S[mt][nt][1] * 0.125f : -1e30f;
                S[mt][nt][2] = v0 ? S[mt][nt][2] * 0.125f : -1e30f;
                S[mt][nt][3] = v1 ? S[mt][nt][3] * 0.125f : -1e30f;
            }

            float t0 = -1e30f, t1 = -1e30f;
            #pragma unroll
            for (int nt = 0; nt < 8; nt++) {
                t0 = fmaxf(t0, fmaxf(S[mt][nt][0], S[mt][nt][1]));
                t1 = fmaxf(t1, fmaxf(S[mt][nt][2], S[mt][nt][3]));
            }
            t0 = fmaxf(t0, __shfl_xor_sync(0xffffffffu, t0, 1));
            t0 = fmaxf(t0, __shfl_xor_sync(0xffffffffu, t0, 2));
            t1 = fmaxf(t1, __shfl_xor_sync(0xffffffffu, t1, 1));
            t1 = fmaxf(t1, __shfl_xor_sync(0xffffffffu, t1, 2));

            const float mn0 = fmaxf(mrow[mt][0], t0), mn1 = fmaxf(mrow[mt][1], t1);
            const float al0 = __expf(mrow[mt][0] - mn0), al1 = __expf(mrow[mt][1] - mn1);
            mrow[mt][0] = mn0; mrow[mt][1] = mn1;

            float rs0 = 0.f, rs1 = 0.f;
            #pragma unroll
            for (int nt = 0; nt < 8; nt++) {
                S[mt][nt][0] = __expf(S[mt][nt][0] - mn0);
                S[mt][nt][1] = __expf(S[mt][nt][1] - mn0);
                S[mt][nt][2] = __expf(S[mt][nt][2] - mn1);
                S[mt][nt][3] = __expf(S[mt][nt][3] - mn1);
                rs0 += S[mt][nt][0] + S[mt][nt][1];
                rs1 += S[mt][nt][2] + S[mt][nt][3];
            }
            rs0 += __shfl_xor_sync(0xffffffffu, rs0, 1);
            rs0 += __shfl_xor_sync(0xffffffffu, rs0, 2);
            rs1 += __shfl_xor_sync(0xffffffffu, rs1, 1);
            rs1 += __shfl_xor_sync(0xffffffffu, rs1, 2);
            lrow[mt][0] = lrow[mt][0] * al0 + rs0;
            lrow[mt][1] = lrow[mt][1] * al1 + rs1;

            #pragma unroll
            for (int nt = 0; nt < 8; nt++) {
                O[mt][nt][0] *= al0; O[mt][nt][1] *= al0;
                O[mt][nt][2] *= al1; O[mt][nt][3] *= al1;
            }
        }

        // pack P into A-fragments (hi + lo)
        uint32_t ph[2][4][4], pl[2][4][4];
        #pragma unroll
        for (int mt = 0; mt < 2; mt++) {
            #pragma unroll
            for (int ks = 0; ks < 4; ks++) {
                pack_hilo(S[mt][2*ks][0],   S[mt][2*ks][1],   ph[mt][ks][0], pl[mt][ks][0]);
                pack_hilo(S[mt][2*ks][2],   S[mt][2*ks][3],   ph[mt][ks][1], pl[mt][ks][1]);
                pack_hilo(S[mt][2*ks+1][0], S[mt][2*ks+1][1], ph[mt][ks][2], pl[mt][ks][2]);
                pack_hilo(S[mt][2*ks+1][2], S[mt][2*ks+1][3], ph[mt][ks][3], pl[mt][ks][3]);
            }
        }

        // ---- PV: O += P @ V (3-term split) ----
        #pragma unroll
        for (int ks = 0; ks < 4; ks++) {
            uint32_t vh2[8][2], vl2[8][2];
            #pragma unroll
            for (int np = 0; np < 4; np++) {
                uint32_t th[4], tl[4];
                ldsm4(th, vhBase + np * (16 * VPITCH * 2) + ks * 32);
                ldsm4(tl, vlBase + np * (16 * VPITCH * 2) + ks * 32);
                vh2[2*np][0] = th[0]; vh2[2*np][1] = th[1];
                vh2[2*np+1][0] = th[2]; vh2[2*np+1][1] = th[3];
                vl2[2*np][0] = tl[0]; vl2[2*np][1] = tl[1];
                vl2[2*np+1][0] = tl[2]; vl2[2*np+1][1] = tl[3];
            }
            #pragma unroll
            for (int nt = 0; nt < 8; nt++) {
                #pragma unroll
                for (int mt = 0; mt < 2; mt++) {
                    mma16816(O[mt][nt], ph[mt][ks], vh2[nt]);
                    mma16816(O[mt][nt], ph[mt][ks], vl2[nt]);
                    mma16816(O[mt][nt], pl[mt][ks], vh2[nt]);
                }
            }
        }
    }

    // epilogue
    const int b = bh / H_, h = bh - b * H_;
    #pragma unroll
    for (int mt = 0; mt < 2; mt++) {
        const float inv0 = 1.f / lrow[mt][0], inv1 = 1.f / lrow[mt][1];
        const int row0 = b * NTOK + TTXT + q0 + wrow + mt * 16 + g;
        const int row1 = row0 + 8;
        #pragma unroll
        for (int nt = 0; nt < 8; nt++) {
            const int c = h * HD + nt * 8 + tg * 2;
            store_split3(row0, c,     O[mt][nt][0] * inv0);
            store_split3(row0, c + 1, O[mt][nt][1] * inv0);
            store_split3(row1, c,     O[mt][nt][2] * inv1);
            store_split3(row1, c + 1, O[mt][nt][3] * inv1);
        }
    }
}

// ---------------- launch ----------------
extern "C" void kernel_launch(void* const* d_in, const int* in_sizes, int n_in,
                              void* d_out, int out_size)
{
    const float* x      = (const float*)d_in[0];
    const float* qkv_w  = (const float*)d_in[1];
    const float* proj_w = (const float*)d_in[2];
    const float* proj_b = (const float*)d_in[3];
    float* out = (float*)d_out;

    cudaFuncSetAttribute(img_attn_mma_kernel,
                         cudaFuncAttributeMaxDynamicSharedMemorySize, IMG_SMEM2);
    cudaFuncSetAttribute(qkv_gemm_kernel,
                         cudaFuncAttributeMaxDynamicSharedMemorySize, GEMM_SMEM);
    cudaFuncSetAttribute(proj_gemm_kernel,
                         cudaFuncAttributeMaxDynamicSharedMemorySize, GEMM_SMEM);

    split_x_kernel <<<(MPAD*CDIM + 255)/256, 256>>>(x);
    split_w1_kernel<<<(NQKV*CDIM + 255)/256, 256>>>(qkv_w);
    split_w2_kernel<<<(CDIM*CDIM + 255)/256, 256>>>(proj_w);

    qkv_gemm_kernel<<<dim3(NQKV/128, MPAD/128), 128, GEMM_SMEM>>>();

    text_attn_kernel<<<B_*H_, 64>>>();
    img_attn_mma_kernel<<<dim3(SIMG/128, B_*H_), 128, IMG_SMEM2>>>();

    proj_gemm_kernel<<<dim3(CDIM/128, MPAD/128), 128, GEMM_SMEM>>>(proj_b, out);
}

// round 10
// speedup vs baseline: 4.2894x; 1.0115x over previous
#include <cuda_runtime.h>
#include <cuda_bf16.h>
#include <cstdint>

// ---------------- problem constants ----------------
#define B_    8
#define TTXT  40
#define SIMG  1024
#define NTOK  1064
#define CDIM  768
#define H_    12
#define HD    64
#define MROWS (B_*NTOK)       // 8512
#define MPAD  8576            // 67*128
#define K3    (3*CDIM)        // 2304
#define NQKV  (3*CDIM)        // 2304

// ---------------- device scratch (referenced ONLY from device code) ----------------
__device__ float g_q [B_*H_*NTOK*HD];
__device__ float g_k [B_*H_*NTOK*HD];
__device__ float g_v [B_*H_*NTOK*HD];

__device__ __align__(16) __nv_bfloat16 gxc [MPAD*K3];
__device__ __align__(16) __nv_bfloat16 gw1c[NQKV*K3];
__device__ __align__(16) __nv_bfloat16 gw2c[CDIM*K3];
__device__ __align__(16) __nv_bfloat16 gaoc[MPAD*K3];

__device__ __align__(16) __nv_bfloat16 g_qc [B_*H_*NTOK*192];  // [bh][n][hi|hi|lo]
__device__ __align__(16) __nv_bfloat16 g_kc [B_*H_*NTOK*192];  // [bh][n][hi|lo|hi]
__device__ __align__(16) __nv_bfloat16 g_vht[B_*H_*HD*NTOK];   // V^T hi: [bh][e][n]
__device__ __align__(16) __nv_bfloat16 g_vlt[B_*H_*HD*NTOK];   // V^T lo

// ---------------- split/concat kernels ----------------
__global__ __launch_bounds__(256) void split_x_kernel(const float* __restrict__ src)
{
    int i = blockIdx.x * 256 + threadIdx.x;
    if (i >= MPAD * CDIM) return;
    int row = i / CDIM, c = i - row * CDIM;
    float f = (row < MROWS) ? src[(size_t)row * CDIM + c] : 0.f;
    __nv_bfloat16 h = __float2bfloat16(f);
    __nv_bfloat16 l = __float2bfloat16(f - __bfloat162float(h));
    size_t base = (size_t)row * K3 + c;
    gxc[base]          = h;
    gxc[base + CDIM]   = h;
    gxc[base + 2*CDIM] = l;
}

__global__ __launch_bounds__(256) void split_w1_kernel(const float* __restrict__ src)
{
    int i = blockIdx.x * 256 + threadIdx.x;
    if (i >= NQKV * CDIM) return;
    int row = i / CDIM, c = i - row * CDIM;
    float f = src[(size_t)row * CDIM + c];
    __nv_bfloat16 h = __float2bfloat16(f);
    __nv_bfloat16 l = __float2bfloat16(f - __bfloat162float(h));
    size_t base = (size_t)row * K3 + c;
    gw1c[base]          = h;
    gw1c[base + CDIM]   = l;
    gw1c[base + 2*CDIM] = h;
}

__global__ __launch_bounds__(256) void split_w2_kernel(const float* __restrict__ src)
{
    int i = blockIdx.x * 256 + threadIdx.x;
    if (i >= CDIM * CDIM) return;
    int row = i / CDIM, c = i - row * CDIM;
    float f = src[(size_t)row * CDIM + c];
    __nv_bfloat16 h = __float2bfloat16(f);
    __nv_bfloat16 l = __float2bfloat16(f - __bfloat162float(h));
    size_t base = (size_t)row * K3 + c;
    gw2c[base]          = h;
    gw2c[base + CDIM]   = l;
    gw2c[base + 2*CDIM] = h;
}

// ---------------- warp mma + ldmatrix + cp.async ----------------
__device__ __forceinline__ void mma16816(float* d, const uint32_t* a, const uint32_t* b)
{
    asm volatile(
        "mma.sync.aligned.m16n8k16.row.col.f32.bf16.bf16.f32 "
        "{%0,%1,%2,%3}, {%4,%5,%6,%7}, {%8,%9}, {%0,%1,%2,%3};"
        : "+f"(d[0]), "+f"(d[1]), "+f"(d[2]), "+f"(d[3])
        : "r"(a[0]), "r"(a[1]), "r"(a[2]), "r"(a[3]), "r"(b[0]), "r"(b[1]));
}

__device__ __forceinline__ void ldsm4(uint32_t* r, uint32_t addr)
{
    asm volatile("ldmatrix.sync.aligned.m8n8.x4.shared.b16 {%0,%1,%2,%3}, [%4];"
        : "=r"(r[0]), "=r"(r[1]), "=r"(r[2]), "=r"(r[3]) : "r"(addr));
}

__device__ __forceinline__ void cpa16(uint32_t dst, const void* src)
{
    asm volatile("cp.async.cg.shared.global [%0], [%1], 16;" :: "r"(dst), "l"(src));
}
#define CP_COMMIT() asm volatile("cp.async.commit_group;" ::: "memory")
#define CP_WAIT(n)  asm volatile("cp.async.wait_group %0;" :: "n"(n) : "memory")

// D[128,128] = A[rows@m0][K3] @ B[rows@n0][K3]^T, fp32 accum.
// 128 threads, 4 warps 2x2, warp tile 64x64. 3-stage cp.async pipeline,
// ONE __syncthreads per K-tile (prefetch issued after the barrier).
#define GSTG  10240                  // bytes per matrix per stage (128*40*2)
#define GEMM_SMEM (6 * GSTG)         // 61440

__device__ __forceinline__ void gemm_main(const __nv_bfloat16* __restrict__ A,
                                          const __nv_bfloat16* __restrict__ B,
                                          int m0, int n0, float acc[4][8][4],
                                          char* gsm)
{
    const int tid  = threadIdx.x;
    const int lane = tid & 31, wid = tid >> 5;
    const int wm = (wid & 1) * 64;
    const int wn = (wid >> 1) * 64;

    const int lr = tid >> 2;          // 0..31
    const int lkb = (tid & 3) * 16;   // byte col offset: 0,16,32,48

    const uint32_t smA = (uint32_t)__cvta_generic_to_shared(gsm);
    const uint32_t smB = smA + 3 * GSTG;

    const char* Ap = (const char*)(A + (size_t)(m0 + lr) * K3) + lkb;
    const char* Bp = (const char*)(B + (size_t)(n0 + lr) * K3) + lkb;

    const uint32_t dA = smA + lr * 80 + lkb;
    const uint32_t dB = smB + lr * 80 + lkb;

    const uint32_t aBase = smA + (wm + (lane & 15)) * 80 + (lane >> 4) * 16;
    const uint32_t bBase = smB + (wn + ((lane >> 4) * 8) + (lane & 7)) * 80
                               + ((lane >> 3) & 1) * 16;

    const int NKI = K3 / 32;          // 72

    // prologue: stages 0,1
    #pragma unroll
    for (int p = 0; p < 2; p++) {
        const size_t o = (size_t)p * 64;
        #pragma unroll
        for (int i = 0; i < 4; i++) {
            cpa16(dA + p * GSTG + (32*i) * 80, Ap + o + (size_t)(32*i) * K3 * 2);
            cpa16(dB + p * GSTG + (32*i) * 80, Bp + o + (size_t)(32*i) * K3 * 2);
        }
        CP_COMMIT();
    }

    for (int t = 0; t < NKI; t++) {
        // stage t%3 data ready: pending groups {g_t, g_{t+1}} -> wait to <=1
        if (t + 1 < NKI) { CP_WAIT(1); } else { CP_WAIT(0); }
        __syncthreads();    // single collective point: all reads of stage (t-3)%3 done

        if (t + 2 < NKI) {  // prefetch stage (t+2)%3 (distinct from read stage t%3)
            const int s = (t + 2) % 3;
            const size_t o = (size_t)(t + 2) * 64;
            #pragma unroll
            for (int i = 0; i < 4; i++) {
                cpa16(dA + s * GSTG + (32*i) * 80, Ap + o + (size_t)(32*i) * K3 * 2);
                cpa16(dB + s * GSTG + (32*i) * 80, Bp + o + (size_t)(32*i) * K3 * 2);
            }
            CP_COMMIT();
        }

        const uint32_t aB = aBase + (t % 3) * GSTG;
        const uint32_t bB = bBase + (t % 3) * GSTG;
        #pragma unroll
        for (int ks = 0; ks < 2; ks++) {
            uint32_t af[4][4], bfr[8][2];
            #pragma unroll
            for (int mt = 0; mt < 4; mt++)
                ldsm4(af[mt], aB + mt * (16 * 80) + ks * 32);
            #pragma unroll
            for (int np = 0; np < 4; np++) {
                uint32_t tmp[4];
                ldsm4(tmp, bB + np * (16 * 80) + ks * 32);
                bfr[2*np][0]   = tmp[0];
                bfr[2*np][1]   = tmp[1];
                bfr[2*np+1][0] = tmp[2];
                bfr[2*np+1][1] = tmp[3];
            }
            #pragma unroll
            for (int mt = 0; mt < 4; mt++)
                #pragma unroll
                for (int nt = 0; nt < 8; nt++)
                    mma16816(acc[mt][nt], af[mt], bfr[nt]);
        }
    }
}

// ---------------- QKV GEMM: epilogue writes attention-ready layouts ----------------
__global__ __launch_bounds__(128) void qkv_gemm_kernel()
{
    extern __shared__ char gsm[];
    const int n0 = blockIdx.x * 128;
    const int m0 = blockIdx.y * 128;

    float acc[4][8][4] = {};
    gemm_main(gxc, gw1c, m0, n0, acc, gsm);

    const int lane = threadIdx.x & 31, wid = threadIdx.x >> 5;
    const int wm = (wid & 1) * 64, wn = (wid >> 1) * 64;
    const int g = lane >> 2, tg = lane & 3;

    const int s3    = n0 / CDIM;
    const int nrem0 = n0 - s3 * CDIM;

    #pragma unroll
    for (int mt = 0; mt < 4; mt++) {
        #pragma unroll
        for (int nt = 0; nt < 8; nt++) {
            const int col = nrem0 + wn + nt * 8 + tg * 2;
            const int hh = col >> 6, e = col & 63;
            #pragma unroll
            for (int rr = 0; rr < 2; rr++) {
                const int mm = m0 + wm + mt * 16 + g + rr * 8;
                if (mm >= MROWS) continue;
                const int b = mm / NTOK;
                const int n = mm - b * NTOK;
                const size_t idx = (size_t)(b * H_ + hh) * NTOK + n;
                const float v0 = acc[mt][nt][rr * 2 + 0];
                const float v1 = acc[mt][nt][rr * 2 + 1];
                const __nv_bfloat16 h0 = __float2bfloat16(v0);
                const __nv_bfloat16 h1 = __float2bfloat16(v1);
                const __nv_bfloat16 l0 = __float2bfloat16(v0 - __bfloat162float(h0));
                const __nv_bfloat16 l1 = __float2bfloat16(v1 - __bfloat162float(h1));
                if (s3 == 0) {
                    __nv_bfloat16* qd = g_qc + idx * 192 + e;
                    qd[0]   = h0; qd[1]   = h1;
                    qd[64]  = h0; qd[65]  = h1;
                    qd[128] = l0; qd[129] = l1;
                    if (n < TTXT) { g_q[idx*HD + e] = v0; g_q[idx*HD + e + 1] = v1; }
                } else if (s3 == 1) {
                    __nv_bfloat16* kd = g_kc + idx * 192 + e;
                    kd[0]   = h0; kd[1]   = h1;
                    kd[64]  = l0; kd[65]  = l1;
                    kd[128] = h0; kd[129] = h1;
                    if (n < TTXT) { g_k[idx*HD + e] = v0; g_k[idx*HD + e + 1] = v1; }
                } else {
                    const size_t vi = ((size_t)(b * H_ + hh) * HD + e) * NTOK + n;
                    g_vht[vi]        = h0;
                    g_vht[vi + NTOK] = h1;
                    g_vlt[vi]        = l0;
                    g_vlt[vi + NTOK] = l1;
                    if (n < TTXT) { g_v[idx*HD + e] = v0; g_v[idx*HD + e + 1] = v1; }
                }
            }
        }
    }
}

// ---------------- proj GEMM kernel ----------------
__global__ __launch_bounds__(128) void proj_gemm_kernel(const float* __restrict__ bias,
                                                        float* __restrict__ out)
{
    extern __shared__ char gsm[];
    const int n0 = blockIdx.x * 128;
    const int m0 = blockIdx.y * 128;

    float acc[4][8][4] = {};
    gemm_main(gaoc, gw2c, m0, n0, acc, gsm);

    const int lane = threadIdx.x & 31, wid = threadIdx.x >> 5;
    const int wm = (wid & 1) * 64, wn = (wid >> 1) * 64;
    const int g = lane >> 2, tg = lane & 3;

    #pragma unroll
    for (int mt = 0; mt < 4; mt++) {
        #pragma unroll
        for (int nt = 0; nt < 8; nt++) {
            const int d = n0 + wn + nt * 8 + tg * 2;
            const float b0 = bias[d], b1 = bias[d + 1];
            #pragma unroll
            for (int rr = 0; rr < 2; rr++) {
                const int m = m0 + wm + mt * 16 + g + rr * 8;
                if (m >= MROWS) continue;
                out[(size_t)m * CDIM + d]     = acc[mt][nt][rr * 2 + 0] + b0;
                out[(size_t)m * CDIM + d + 1] = acc[mt][nt][rr * 2 + 1] + b1;
            }
        }
    }
}

// ---------------- gaoc split-store (A-side hi|hi|lo) ----------------
__device__ __forceinline__ void store_split3(int row, int c, float v)
{
    __nv_bfloat16 h = __float2bfloat16(v);
    __nv_bfloat16 l = __float2bfloat16(v - __bfloat162float(h));
    size_t base = (size_t)row * K3 + c;
    gaoc[base]          = h;
    gaoc[base + CDIM]   = h;
    gaoc[base + 2*CDIM] = l;
}

// ---------------- text attention (fp32, tiny) ----------------
__global__ __launch_bounds__(64) void text_attn_kernel()
{
    const int bh = blockIdx.x;
    const int b = bh / H_;
    const int h = bh - b * H_;

    __shared__ float Kt[TTXT][HD];
    __shared__ float Vt[TTXT][HD];

    const size_t base = (size_t)(b*H_ + h) * NTOK * HD;
    const float* kbase = g_k + base;
    const float* vbase = g_v + base;

    const int tid = threadIdx.x;
    for (int i = tid; i < TTXT*HD; i += 64) {
        Kt[i / HD][i % HD] = kbase[i];
        Vt[i / HD][i % HD] = vbase[i];
    }
    __syncthreads();

    if (tid < TTXT) {
        const float* qrow = g_q + base + (size_t)tid * HD;
        float qv[HD];
        #pragma unroll
        for (int e = 0; e < HD; e++) qv[e] = qrow[e];

        float sc[TTXT];
        float mx = -1e30f;
        #pragma unroll 4
        for (int s = 0; s < TTXT; s++) {
            float d = 0.f;
            #pragma unroll
            for (int e = 0; e < HD; e++) d += qv[e] * Kt[s][e];
            d *= 0.125f;
            sc[s] = d;
            mx = fmaxf(mx, d);
        }
        float sum = 0.f;
        #pragma unroll
        for (int s = 0; s < TTXT; s++) { sc[s] = __expf(sc[s] - mx); sum += sc[s]; }
        float inv = 1.f / sum;

        const int row = b * NTOK + tid;
        #pragma unroll 4
        for (int e = 0; e < HD; e++) {
            float a = 0.f;
            #pragma unroll
            for (int s = 0; s < TTXT; s++) a += sc[s] * Vt[s][e];
            store_split3(row, h * HD + e, a * inv);
        }
    }
}

// ---------------- image attention: mma flash kernel (128-query blocks) ----------------
#define QPITCH 200
#define VPITCH 72
#define OFF_K  51200
#define OFF_VH 76800
#define OFF_VL 86016
#define IMG_SMEM2 95232

__device__ __forceinline__ void pack_hilo(float x, float y, uint32_t& hi, uint32_t& lo)
{
    __nv_bfloat162 h = __floats2bfloat162_rn(x, y);
    float hx = __bfloat162float(h.x), hy = __bfloat162float(h.y);
    __nv_bfloat162 l = __floats2bfloat162_rn(x - hx, y - hy);
    hi = *(uint32_t*)&h;
    lo = *(uint32_t*)&l;
}

__global__ __launch_bounds__(128) void img_attn_mma_kernel()
{
    extern __shared__ char smx[];
    __nv_bfloat16* Qs = (__nv_bfloat16*)(smx);            // [128][200]
    __nv_bfloat16* Ks = (__nv_bfloat16*)(smx + OFF_K);    // [64][200]
    __nv_bfloat16* Vh = (__nv_bfloat16*)(smx + OFF_VH);   // [64][72]
    __nv_bfloat16* Vl = (__nv_bfloat16*)(smx + OFF_VL);   // [64][72]

    const int bh = blockIdx.y;
    const int q0 = blockIdx.x * 128;
    const int tid = threadIdx.x;
    const int lane = tid & 31, wid = tid >> 5;
    const int g = lane >> 2, tg = lane & 3;
    const int wrow = wid * 32;            // 32 query rows per warp (mt=2)

    const uint32_t ksAddr = (uint32_t)__cvta_generic_to_shared(Ks);
    const uint32_t vhAddr = (uint32_t)__cvta_generic_to_shared(Vh);
    const uint32_t vlAddr = (uint32_t)__cvta_generic_to_shared(Vl);

    const uint32_t qBase = (uint32_t)__cvta_generic_to_shared(
        Qs + (wrow + (lane & 15)) * QPITCH + (lane >> 4) * 8);
    const uint32_t kBase = ksAddr
        + ((((lane >> 4) * 8) + (lane & 7)) * QPITCH + ((lane >> 3) & 1) * 8) * 2;
    const uint32_t vhBase = vhAddr
        + ((((lane >> 4) * 8) + (lane & 7)) * VPITCH + ((lane >> 3) & 1) * 8) * 2;
    const uint32_t vlBase = vlAddr
        + ((((lane >> 4) * 8) + (lane & 7)) * VPITCH + ((lane >> 3) & 1) * 8) * 2;

    // load Q tile (128 rows x 192)
    {
        const __nv_bfloat16* qsrc = g_qc + ((size_t)bh * NTOK + TTXT + q0) * 192;
        for (int u = tid; u < 128 * 24; u += 128) {
            int r = u / 24, o = (u % 24) * 8;
            *(uint4*)&Qs[r * QPITCH + o] = *(const uint4*)(qsrc + (size_t)r * 192 + o);
        }
    }

    float mrow[2][2], lrow[2][2];
    #pragma unroll
    for (int mt = 0; mt < 2; mt++) { mrow[mt][0] = mrow[mt][1] = -1e30f; lrow[mt][0] = lrow[mt][1] = 0.f; }

    float O[2][8][4];
    #pragma unroll
    for (int mt = 0; mt < 2; mt++)
        #pragma unroll
        for (int nt = 0; nt < 8; nt++)
            #pragma unroll
            for (int j = 0; j < 4; j++) O[mt][nt][j] = 0.f;

    const __nv_bfloat16* kcb = g_kc + (size_t)bh * NTOK * 192;
    const __nv_bfloat16* vhb = g_vht + (size_t)bh * HD * NTOK;
    const __nv_bfloat16* vlb = g_vlt + (size_t)bh * HD * NTOK;

    for (int t = 0; t < 17; t++) {
        const int j0 = t * 64;
        __syncthreads();

        for (int u = tid; u < 64 * 24; u += 128) {
            int r = u / 24, o = (u % 24) * 8;
            if (j0 + r < NTOK)
                cpa16(ksAddr + (r * QPITCH + o) * 2, kcb + (size_t)(j0 + r) * 192 + o);
            else
                *(uint4*)&Ks[r * QPITCH + o] = make_uint4(0u, 0u, 0u, 0u);
        }
        for (int u = tid; u < 64 * 8; u += 128) {
            int e = u >> 3, o = (u & 7) * 8;
            if (j0 + o + 7 < NTOK) {
                cpa16(vhAddr + (e * VPITCH + o) * 2, vhb + (size_t)e * NTOK + j0 + o);
                cpa16(vlAddr + (e * VPITCH + o) * 2, vlb + (size_t)e * NTOK + j0 + o);
            } else {
                *(uint4*)&Vh[e * VPITCH + o] = make_uint4(0u, 0u, 0u, 0u);
                *(uint4*)&Vl[e * VPITCH + o] = make_uint4(0u, 0u, 0u, 0u);
            }
        }
        CP_COMMIT();
        CP_WAIT(0);
        __syncthreads();

        float S[2][8][4];
        #pragma unroll
        for (int mt = 0; mt < 2; mt++)
            #pragma unroll
            for (int nt = 0; nt < 8; nt++)
                #pragma unroll
                for (int j = 0; j < 4; j++) S[mt][nt][j] = 0.f;

        #pragma unroll
        for (int ks = 0; ks < 12; ks++) {
            uint32_t a[2][4];
            ldsm4(a[0], qBase + ks * 32);
            ldsm4(a[1], qBase + 16 * (QPITCH * 2) + ks * 32);
            uint32_t bfr[8][2];
            #pragma unroll
            for (int np = 0; np < 4; np++) {
                uint32_t tmp[4];
                ldsm4(tmp, kBase + np * (16 * QPITCH * 2) + ks * 32);
                bfr[2*np][0]   = tmp[0];
                bfr[2*np][1]   = tmp[1];
                bfr[2*np+1][0] = tmp[2];
                bfr[2*np+1][1] = tmp[3];
            }
            #pragma unroll
            for (int nt = 0; nt < 8; nt++) {
                mma16816(S[0][nt], a[0], bfr[nt]);
                mma16816(S[1][nt], a[1], bfr[nt]);
            }
        }

        #pragma unroll
        for (int mt = 0; mt < 2; mt++) {
            #pragma unroll
            for (int nt = 0; nt < 8; nt++) {
                const int key = j0 + nt * 8 + tg * 2;
                const bool v0 = key < NTOK, v1 = key + 1 < NTOK;
                S[mt][nt][0] = v0 ? S[mt][nt][0] * 0.125f : -1e30f;
                S[mt][nt][1] = v1 ? S[mt][nt][1] * 0.125f : -1e30f;
                S[mt][nt][2] = v0 ? S[mt][nt][2] * 0.125f : -1e30f;
                S[mt][nt][3] = v1 ? S[mt][nt][3] * 0.125f : -1e30f;
            }

            float t0 = -1e30f, t1 = -1e30f;
            #pragma unroll
            for (int nt = 0; nt < 8; nt++) {
                t0 = fmaxf(t0, fmaxf(S[mt][nt][0], S[mt][nt][1]));
                t1 = fmaxf(t1, fmaxf(S[mt][nt][2], S[mt][nt][3]));
            }
            t0 = fmaxf(t0, __shfl_xor_sync(0xffffffffu, t0, 1));
            t0 = fmaxf(t0, __shfl_xor_sync(0xffffffffu, t0, 2));
            t1 = fmaxf(t1, __shfl_xor_sync(0xffffffffu, t1, 1));
            t1 = fmaxf(t1, __shfl_xor_sync(0xffffffffu, t1, 2));

            const float mn0 = fmaxf(mrow[mt][0], t0), mn1 = fmaxf(mrow[mt][1], t1);
            const float al0 = __expf(mrow[mt][0] - mn0), al1 = __expf(mrow[mt][1] - mn1);
            mrow[mt][0] = mn0; mrow[mt][1] = mn1;

            float rs0 = 0.f, rs1 = 0.f;
            #pragma unroll
            for (int nt = 0; nt < 8; nt++) {
                S[mt][nt][0] = __expf(S[mt][nt][0] - mn0);
                S[mt][nt][1] = __expf(S[mt][nt][1] - mn0);
                S[mt][nt][2] = __expf(S[mt][nt][2] - mn1);
                S[mt][nt][3] = __expf(S[mt][nt][3] - mn1);
                rs0 += S[mt][nt][0] + S[mt][nt][1];
                rs1 += S[mt][nt][2] + S[mt][nt][3];
            }
            rs0 += __shfl_xor_sync(0xffffffffu, rs0, 1);
            rs0 += __shfl_xor_sync(0xffffffffu, rs0, 2);
            rs1 += __shfl_xor_sync(0xffffffffu, rs1, 1);
            rs1 += __shfl_xor_sync(0xffffffffu, rs1, 2);
            lrow[mt][0] = lrow[mt][0] * al0 + rs0;
            lrow[mt][1] = lrow[mt][1] * al1 + rs1;

            #pragma unroll
            for (int nt = 0; nt < 8; nt++) {
                O[mt][nt][0] *= al0; O[mt][nt][1] *= al0;
                O[mt][nt][2] *= al1; O[mt][nt][3] *= al1;
            }
        }

        uint32_t ph[2][4][4], pl[2][4][4];
        #pragma unroll
        for (int mt = 0; mt < 2; mt++) {
            #pragma unroll
            for (int ks = 0; ks < 4; ks++) {
                pack_hilo(S[mt][2*ks][0],   S[mt][2*ks][1],   ph[mt][ks][0], pl[mt][ks][0]);
                pack_hilo(S[mt][2*ks][2],   S[mt][2*ks][3],   ph[mt][ks][1], pl[mt][ks][1]);
                pack_hilo(S[mt][2*ks+1][0], S[mt][2*ks+1][1], ph[mt][ks][2], pl[mt][ks][2]);
                pack_hilo(S[mt][2*ks+1][2], S[mt][2*ks+1][3], ph[mt][ks][3], pl[mt][ks][3]);
            }
        }

        #pragma unroll
        for (int ks = 0; ks < 4; ks++) {
            uint32_t vh2[8][2], vl2[8][2];
            #pragma unroll
            for (int np = 0; np < 4; np++) {
                uint32_t th[4], tl[4];
                ldsm4(th, vhBase + np * (16 * VPITCH * 2) + ks * 32);
                ldsm4(tl, vlBase + np * (16 * VPITCH * 2) + ks * 32);
                vh2[2*np][0] = th[0]; vh2[2*np][1] = th[1];
                vh2[2*np+1][0] = th[2]; vh2[2*np+1][1] = th[3];
                vl2[2*np][0] = tl[0]; vl2[2*np][1] = tl[1];
                vl2[2*np+1][0] = tl[2]; vl2[2*np+1][1] = tl[3];
            }
            #pragma unroll
            for (int nt = 0; nt < 8; nt++) {
                #pragma unroll
                for (int mt = 0; mt < 2; mt++) {
                    mma16816(O[mt][nt], ph[mt][ks], vh2[nt]);
                    mma16816(O[mt][nt], ph[mt][ks], vl2[nt]);
                    mma16816(O[mt][nt], pl[mt][ks], vh2[nt]);
                }
            }
        }
    }

    // epilogue
    const int b = bh / H_, h = bh - b * H_;
    #pragma unroll
    for (int mt = 0; mt < 2; mt++) {
        const float inv0 = 1.f / lrow[mt][0], inv1 = 1.f / lrow[mt][1];
        const int row0 = b * NTOK + TTXT + q0 + wrow + mt * 16 + g;
        const int row1 = row0 + 8;
        #pragma unroll
        for (int nt = 0; nt < 8; nt++) {
            const int c = h * HD + nt * 8 + tg * 2;
            store_split3(row0, c,     O[mt][nt][0] * inv0);
            store_split3(row0, c + 1, O[mt][nt][1] * inv0);
            store_split3(row1, c,     O[mt][nt][2] * inv1);
            store_split3(row1, c + 1, O[mt][nt][3] * inv1);
        }
    }
}

// ---------------- launch ----------------
extern "C" void kernel_launch(void* const* d_in, const int* in_sizes, int n_in,
                              void* d_out, int out_size)
{
    const float* x      = (const float*)d_in[0];
    const float* qkv_w  = (const float*)d_in[1];
    const float* proj_w = (const float*)d_in[2];
    const float* proj_b = (const float*)d_in[3];
    float* out = (float*)d_out;

    cudaFuncSetAttribute(img_attn_mma_kernel,
                         cudaFuncAttributeMaxDynamicSharedMemorySize, IMG_SMEM2);
    cudaFuncSetAttribute(qkv_gemm_kernel,
                         cudaFuncAttributeMaxDynamicSharedMemorySize, GEMM_SMEM);
    cudaFuncSetAttribute(proj_gemm_kernel,
                         cudaFuncAttributeMaxDynamicSharedMemorySize, GEMM_SMEM);

    split_x_kernel <<<(MPAD*CDIM + 255)/256, 256>>>(x);
    split_w1_kernel<<<(NQKV*CDIM + 255)/256, 256>>>(qkv_w);
    split_w2_kernel<<<(CDIM*CDIM + 255)/256, 256>>>(proj_w);

    qkv_gemm_kernel<<<dim3(NQKV/128, MPAD/128), 128, GEMM_SMEM>>>();

    text_attn_kernel<<<B_*H_, 64>>>();
    img_attn_mma_kernel<<<dim3(SIMG/128, B_*H_), 128, IMG_SMEM2>>>();

    proj_gemm_kernel<<<dim3(CDIM/128, MPAD/128), 128, GEMM_SMEM>>>(proj_b, out);
}